// round 1
// baseline (speedup 1.0000x reference)
#include <cuda_runtime.h>
#include <math.h>

#define NB 16
#define NL 512
#define ND 512
#define NCB 4096
#define NTOT (NB*NL*ND)

// ---------------- scratch (device globals: allocation-free) ----------------
__device__ float g_resid[NTOT];                    // 16 MB
__device__ float g_z[NTOT];                        // 16 MB (downsampled residual, max s=512)
__device__ float g_qup[NTOT];                      // 16 MB (upsampled dequant, pre-Phi)
__device__ unsigned long long g_keys[NB*NL];       // packed (score,idx) per token
__device__ float g_esq[NCB];                       // ||e_c||^2
__device__ float g_wt[4*3*ND*ND];                  // phi weights transposed: [p][k][i][o]

// ---------------- setup kernels ----------------
__global__ void k_setup_esq(const float* __restrict__ embed) {
    int gw = (blockIdx.x * blockDim.x + threadIdx.x) >> 5;
    int lane = threadIdx.x & 31;
    if (gw >= NCB) return;
    const float* e = embed + gw * ND;
    float s = 0.f;
    for (int d = lane; d < ND; d += 32) { float v = e[d]; s = fmaf(v, v, s); }
    for (int o = 16; o > 0; o >>= 1) s += __shfl_xor_sync(0xffffffffu, s, o);
    if (lane == 0) g_esq[gw] = s;
}

__global__ void k_setup_wt(const float* __restrict__ phi_w) {
    int total = 4 * 3 * ND * ND;
    for (int t = blockIdx.x * blockDim.x + threadIdx.x; t < total;
         t += gridDim.x * blockDim.x) {
        int o = t & 511;
        int r = t >> 9;
        int i = r & 511; r >>= 9;
        int k = r % 3;
        int p = r / 3;
        // g_wt[((p*3+k)*512+i)*512+o] = phi_w[p][o][i][k]
        g_wt[t] = phi_w[((p * ND + o) * ND + i) * 3 + k];
    }
}

__global__ void k_init(const float* __restrict__ x, float* __restrict__ out) {
    for (int t = blockIdx.x * blockDim.x + threadIdx.x; t < NTOT;
         t += gridDim.x * blockDim.x) {
        g_resid[t] = x[t];
        out[t] = 0.f;
    }
}

// ---------------- downsample: block mean, also reset argmin keys ----------------
__global__ void k_down(int s) {
    int r = NL / s;
    float inv = 1.0f / (float)r;   // r power of two -> exact
    int total = NB * s * ND;
    for (int t = blockIdx.x * blockDim.x + threadIdx.x; t < total;
         t += gridDim.x * blockDim.x) {
        int d = t & 511;
        int bt = t >> 9;
        int b = bt / s, tt = bt % s;
        const float* src = g_resid + (b * NL + tt * r) * ND + d;
        float acc = 0.f;
        for (int j = 0; j < r; j++) acc += src[j * ND];
        g_z[t] = acc * inv;
        if (d == 0) g_keys[bt] = 0xFFFFFFFFFFFFFFFFULL;
    }
}

// ---------------- quantize: tiled fp32 GEMM + running argmin + atomicMin merge ----
__global__ __launch_bounds__(256) void k_quant(const float* __restrict__ embed,
                                               int nTok, int cps) {
    __shared__ __align__(16) float As[32][68];
    __shared__ __align__(16) float Bs[32][68];
    int m0 = blockIdx.x * 64;
    int c0 = blockIdx.y * cps;
    int tid = threadIdx.x;
    int tx = tid & 15, ty = tid >> 4;

    float best[4]; int bidx[4];
#pragma unroll
    for (int i = 0; i < 4; i++) { best[i] = 3.4e38f; bidx[i] = 0x7fffffff; }

    for (int cc = 0; cc < cps; cc += 64) {
        int n0 = c0 + cc;
        float acc[4][4];
#pragma unroll
        for (int i = 0; i < 4; i++)
#pragma unroll
            for (int j = 0; j < 4; j++) acc[i][j] = 0.f;

        for (int k0 = 0; k0 < ND; k0 += 32) {
#pragma unroll
            for (int ld = 0; ld < 2; ld++) {
                int flat = tid + (ld << 8);
                int m = flat >> 3;
                int k4 = (flat & 7) << 2;
                int tok = m0 + m;
                float4 av = make_float4(0.f, 0.f, 0.f, 0.f);
                if (tok < nTok)
                    av = *(const float4*)(g_z + tok * ND + k0 + k4);
                As[k4 + 0][m] = av.x; As[k4 + 1][m] = av.y;
                As[k4 + 2][m] = av.z; As[k4 + 3][m] = av.w;
                float4 bv = *(const float4*)(embed + (n0 + m) * ND + k0 + k4);
                Bs[k4 + 0][m] = bv.x; Bs[k4 + 1][m] = bv.y;
                Bs[k4 + 2][m] = bv.z; Bs[k4 + 3][m] = bv.w;
            }
            __syncthreads();
#pragma unroll
            for (int k = 0; k < 32; k++) {
                float4 a = *(const float4*)&As[k][ty << 2];
                float4 b = *(const float4*)&Bs[k][tx << 2];
                float ar[4] = {a.x, a.y, a.z, a.w};
                float br[4] = {b.x, b.y, b.z, b.w};
#pragma unroll
                for (int i = 0; i < 4; i++)
#pragma unroll
                    for (int j = 0; j < 4; j++)
                        acc[i][j] = fmaf(ar[i], br[j], acc[i][j]);
            }
            __syncthreads();
        }

        // score = ||e||^2 - 2 z.e ; running argmin with first-index tie-break
#pragma unroll
        for (int i = 0; i < 4; i++) {
            float lb = 3.4e38f; int li = 0x7fffffff;
#pragma unroll
            for (int j = 0; j < 4; j++) {
                int c = n0 + (tx << 2) + j;
                float sc = fmaf(-2.f, acc[i][j], g_esq[c]);
                if (sc < lb) { lb = sc; li = c; }
            }
            // butterfly reduce across the 16 tx lanes (same half-warp)
            for (int o = 8; o > 0; o >>= 1) {
                float os = __shfl_xor_sync(0xffffffffu, lb, o);
                int   oi = __shfl_xor_sync(0xffffffffu, li, o);
                if (os < lb || (os == lb && oi < li)) { lb = os; li = oi; }
            }
            if (lb < best[i] || (lb == best[i] && li < bidx[i])) {
                best[i] = lb; bidx[i] = li;
            }
        }
    }

    if (tx == 0) {
#pragma unroll
        for (int i = 0; i < 4; i++) {
            int tok = m0 + (ty << 2) + i;
            if (tok < nTok) {
                unsigned u = __float_as_uint(best[i]);
                u = (u & 0x80000000u) ? ~u : (u | 0x80000000u);  // order-preserving map
                unsigned long long key =
                    ((unsigned long long)u << 32) | (unsigned)bidx[i];
                atomicMin(&g_keys[tok], key);
            }
        }
    }
}

// ---------------- dequant gather + half-pixel linear upsample ----------------
__global__ void k_up(const float* __restrict__ embed, int s) {
    float ratio = (float)s * (1.0f / 512.0f);   // power of two -> exact positions
    for (int t = blockIdx.x * blockDim.x + threadIdx.x; t < NTOT;
         t += gridDim.x * blockDim.x) {
        int d = t & 511;
        int bl = t >> 9;
        int b = bl >> 9, l = bl & 511;
        float val;
        if (s == NL) {
            int c = (int)(unsigned)(g_keys[bl] & 0xffffffffULL);
            val = embed[c * ND + d];
        } else {
            const unsigned long long* kb = g_keys + b * s;
            float pos = ((float)l + 0.5f) * ratio - 0.5f;
            float fl = floorf(pos);
            int i0 = (int)fl;
            float f = pos - fl;
            if (i0 < 0) {
                int c = (int)(unsigned)(kb[0] & 0xffffffffULL);
                val = embed[c * ND + d];
            } else if (i0 >= s - 1) {
                int c = (int)(unsigned)(kb[s - 1] & 0xffffffffULL);
                val = embed[c * ND + d];
            } else {
                int ca = (int)(unsigned)(kb[i0] & 0xffffffffULL);
                int cb = (int)(unsigned)(kb[i0 + 1] & 0xffffffffULL);
                val = (1.0f - f) * embed[ca * ND + d] + f * embed[cb * ND + d];
            }
        }
        g_qup[t] = val;
    }
}

// ---------------- Phi conv1d (K=3) as GEMM M=8192,N=512,K=1536 + fused epilogue ----
__global__ __launch_bounds__(256) void k_conv(const float* __restrict__ bias,
                                              int p, float* __restrict__ fhat) {
    __shared__ __align__(16) float As[32][68];
    __shared__ __align__(16) float Bs[32][68];
    const float* wt = g_wt + p * (3 * ND * ND);
    int m0 = blockIdx.x * 64;   // m = b*512 + l
    int n0 = blockIdx.y * 64;   // output channel
    int tid = threadIdx.x;
    int tx = tid & 15, ty = tid >> 4;

    float acc[4][4];
#pragma unroll
    for (int i = 0; i < 4; i++)
#pragma unroll
        for (int j = 0; j < 4; j++) acc[i][j] = 0.f;

    for (int kc = 0; kc < 48; kc++) {       // 3 taps x 16 chunks of 32 channels
        int kk = kc >> 4;                   // conv tap 0..2
        int i0 = (kc & 15) << 5;            // input-channel base
#pragma unroll
        for (int ld = 0; ld < 2; ld++) {
            int flat = tid + (ld << 8);
            // A: shifted qup rows, zero-padded at sequence edges (per batch)
            {
                int m = flat >> 3;
                int k4 = (flat & 7) << 2;
                int gm = m0 + m;
                int b = gm >> 9, l = gm & 511;
                int lsrc = l + kk - 1;
                float4 av = make_float4(0.f, 0.f, 0.f, 0.f);
                if ((unsigned)lsrc < 512u)
                    av = *(const float4*)(g_qup + ((b << 9) + lsrc) * ND + i0 + k4);
                As[k4 + 0][m] = av.x; As[k4 + 1][m] = av.y;
                As[k4 + 2][m] = av.z; As[k4 + 3][m] = av.w;
            }
            // B: transposed weights [k*512+i][o], o contiguous
            {
                int kr = flat >> 4;
                int n4 = (flat & 15) << 2;
                float4 bv = *(const float4*)(wt + ((kk << 9) + i0 + kr) * ND + n0 + n4);
                *(float4*)&Bs[kr][n4] = bv;
            }
        }
        __syncthreads();
#pragma unroll
        for (int k = 0; k < 32; k++) {
            float4 a = *(const float4*)&As[k][ty << 2];
            float4 b = *(const float4*)&Bs[k][tx << 2];
            float ar[4] = {a.x, a.y, a.z, a.w};
            float br[4] = {b.x, b.y, b.z, b.w};
#pragma unroll
            for (int i = 0; i < 4; i++)
#pragma unroll
                for (int j = 0; j < 4; j++)
                    acc[i][j] = fmaf(ar[i], br[j], acc[i][j]);
        }
        __syncthreads();
    }

    // epilogue: q_up*(1-r) + (conv+bias)*r ; f_hat += ; residual -=   (r = 0.5)
#pragma unroll
    for (int i = 0; i < 4; i++) {
        int gm = m0 + (ty << 2) + i;
        int col = n0 + (tx << 2);
        int adr = gm * ND + col;
        float4 q4 = *(const float4*)(g_qup + adr);
        float4 b4 = *(const float4*)(bias + col);
        float4 f4 = *(float4*)(fhat + adr);
        float4 r4 = *(float4*)(g_resid + adr);
        float v0 = 0.5f * q4.x + 0.5f * (acc[i][0] + b4.x);
        float v1 = 0.5f * q4.y + 0.5f * (acc[i][1] + b4.y);
        float v2 = 0.5f * q4.z + 0.5f * (acc[i][2] + b4.z);
        float v3 = 0.5f * q4.w + 0.5f * (acc[i][3] + b4.w);
        f4.x += v0; f4.y += v1; f4.z += v2; f4.w += v3;
        r4.x -= v0; r4.y -= v1; r4.z -= v2; r4.w -= v3;
        *(float4*)(fhat + adr) = f4;
        *(float4*)(g_resid + adr) = r4;
    }
}

// ---------------- host ----------------
extern "C" void kernel_launch(void* const* d_in, const int* in_sizes, int n_in,
                              void* d_out, int out_size) {
    const float* x     = (const float*)d_in[0];
    const float* embed = (const float*)d_in[1];
    const float* phi_w = (const float*)d_in[2];
    const float* phi_b = (const float*)d_in[3];
    float* out = (float*)d_out;

    // Replicate np.linspace(1/12, 11/12, 4) + first-min argmin tie-break in double.
    double start = 1.0 / 3.0 / 4.0;
    double stop  = 1.0 - 1.0 / 3.0 / 4.0;
    double step  = (stop - start) / 3.0;
    double ticks[4] = {start, start + step, start + 2.0 * step, stop};
    int scales[10] = {1, 2, 4, 8, 16, 32, 64, 128, 256, 512};
    int phi_idx[10];
    for (int si = 0; si < 10; si++) {
        double v = (double)si / 9.0;
        int bk = 0; double bd = fabs(ticks[0] - v);
        for (int k = 1; k < 4; k++) {
            double dd = fabs(ticks[k] - v);
            if (dd < bd) { bd = dd; bk = k; }
        }
        phi_idx[si] = bk;
    }

    k_setup_esq<<<512, 256>>>(embed);
    k_setup_wt<<<512, 256>>>(phi_w);
    k_init<<<2048, 256>>>(x, out);

    for (int si = 0; si < 10; si++) {
        int s = scales[si];
        int total = NB * s * ND;
        int blk = (total + 255) / 256; if (blk > 4096) blk = 4096;
        k_down<<<blk, 256>>>(s);

        int nTok = NB * s;
        int tTiles = (nTok + 63) / 64;
        int splits = 256 / tTiles;
        if (splits < 1) splits = 1;
        if (splits > 64) splits = 64;
        k_quant<<<dim3(tTiles, splits), 256>>>(embed, nTok, NCB / splits);

        k_up<<<8192, 256>>>(embed, s);

        k_conv<<<dim3(128, 8), 256>>>(phi_b + phi_idx[si] * ND, phi_idx[si], out);
    }
}

// round 3
// speedup vs baseline: 2.1044x; 2.1044x over previous
#include <cuda_runtime.h>
#include <math.h>
#include <stdint.h>

#define NB 16
#define NL 512
#define ND 512
#define NCB 4096
#define NTOT (NB*NL*ND)

// ---------------- scratch (device globals, allocation-free) ----------------
__device__ float g_resid[NTOT];                        // 16 MB
__device__ float g_z[NTOT];                            // 16 MB (downsampled residual)
__device__ float g_wq[3 * NB * NL * ND];               // 48 MB (per-tap q@W^T, token-major)
__device__ unsigned long long g_keys[NB*NL];           // packed (score,idx)
__device__ float g_esq[NCB];
__device__ float g_wt3[4*3*ND*ND];                     // [p][tap][o][i], i contiguous
__device__ float g_part[NB*32*ND];                     // partial sums for deep downsample

// ---------------- setup ----------------
__global__ void k_setup_esq(const float* __restrict__ embed) {
    int gw = (blockIdx.x * blockDim.x + threadIdx.x) >> 5;
    int lane = threadIdx.x & 31;
    if (gw >= NCB) return;
    const float* e = embed + gw * ND;
    float s = 0.f;
    for (int d = lane; d < ND; d += 32) { float v = e[d]; s = fmaf(v, v, s); }
    for (int o = 16; o > 0; o >>= 1) s += __shfl_xor_sync(0xffffffffu, s, o);
    if (lane == 0) g_esq[gw] = s;
}
__global__ void k_setup_wt3(const float* __restrict__ phi_w) {
    int total = 4 * 3 * ND * ND;
    for (int t = blockIdx.x * blockDim.x + threadIdx.x; t < total;
         t += gridDim.x * blockDim.x) {
        int i = t & 511;
        int q = t >> 9;
        int o = q & 511; q >>= 9;
        int tap = q % 3;
        int p = q / 3;
        g_wt3[t] = phi_w[((p * ND + o) * ND + i) * 3 + tap];
    }
}
__global__ void k_init(const float* __restrict__ x, float* __restrict__ out) {
    for (int t = blockIdx.x * blockDim.x + threadIdx.x; t < NTOT;
         t += gridDim.x * blockDim.x) {
        g_resid[t] = x[t];
        out[t] = 0.f;
    }
}

// ---------------- downsample (block mean) + key reset ----------------
__global__ void k_down(int s) {   // direct path, r = NL/s <= 16
    int r = NL / s;
    float inv = 1.0f / (float)r;
    int total = NB * s * ND;
    for (int t = blockIdx.x * blockDim.x + threadIdx.x; t < total;
         t += gridDim.x * blockDim.x) {
        int d = t & 511;
        int bt = t >> 9;
        int b = bt / s, tt = bt % s;
        const float* src = g_resid + (b * NL + tt * r) * ND + d;
        float acc = 0.f;
        for (int j = 0; j < r; j++) acc += src[j * ND];
        g_z[t] = acc * inv;
        if (d == 0) g_keys[bt] = 0xFFFFFFFFFFFFFFFFULL;
    }
}
__global__ void k_down1(int s, int segs) {   // stage 1: sums of 16 rows
    float4* part = (float4*)g_part;
    int total = NB * s * segs * 128;
    for (int t = blockIdx.x * blockDim.x + threadIdx.x; t < total;
         t += gridDim.x * blockDim.x) {
        int d4 = t & 127;
        int rem = t >> 7;
        int seg = rem % segs;
        int bt = rem / segs;
        int b = bt / s, tt = bt % s;
        int r = NL / s;
        const float4* src = (const float4*)(g_resid + (b * NL + tt * r + seg * 16) * ND) + d4;
        float4 a = make_float4(0.f, 0.f, 0.f, 0.f);
        for (int j = 0; j < 16; j++) {
            float4 v = src[j * 128];
            a.x += v.x; a.y += v.y; a.z += v.z; a.w += v.w;
        }
        part[(bt * segs + seg) * 128 + d4] = a;
    }
}
__global__ void k_down2(int s, int segs) {
    const float4* part = (const float4*)g_part;
    float4* gz = (float4*)g_z;
    float inv = (float)s * (1.0f / (float)NL);
    int total = NB * s * 128;
    for (int t = blockIdx.x * blockDim.x + threadIdx.x; t < total;
         t += gridDim.x * blockDim.x) {
        int d4 = t & 127;
        int bt = t >> 7;
        float4 a = make_float4(0.f, 0.f, 0.f, 0.f);
        for (int sg = 0; sg < segs; sg++) {
            float4 v = part[(bt * segs + sg) * 128 + d4];
            a.x += v.x; a.y += v.y; a.z += v.z; a.w += v.w;
        }
        a.x *= inv; a.y *= inv; a.z *= inv; a.w *= inv;
        gz[bt * 128 + d4] = a;
        if (d4 == 0) g_keys[bt] = 0xFFFFFFFFFFFFFFFFULL;
    }
}

// ---------------- unified 128x128 FFMA GEMM core (8x8 microtile) ----------------
// C[m,n] = sum_k A[m,k] * B[n,k]; GATHER: A rows come from embed[key[m]]
// ARGMIN: epilogue does argmin over n of (esq[n] - 2*C) with atomicMin merge
// else: store C to g_wq[(tap*nTok + m)*512 + n], tap = blockIdx.z
template<bool GATHER, bool ARGMIN>
__global__ __launch_bounds__(256, 1) void k_gemm(const float* __restrict__ embed,
                                                 int nTok, int p) {
    __shared__ __align__(16) float As[16][132];
    __shared__ __align__(16) float Bs[16][132];
    int tid = threadIdx.x;
    int tx = tid & 15, ty = tid >> 4;
    int m0 = blockIdx.x * 128, n0 = blockIdx.y * 128;
    int tap = blockIdx.z;
    const float* Bsrc = ARGMIN ? embed
                               : (g_wt3 + ((p * 3 + tap) * ND) * ND);

    float acc[8][8];
#pragma unroll
    for (int i = 0; i < 8; i++)
#pragma unroll
        for (int j = 0; j < 8; j++) acc[i][j] = 0.f;

    for (int k0 = 0; k0 < ND; k0 += 16) {
#pragma unroll
        for (int it = 0; it < 2; it++) {
            int idx = tid + (it << 8);
            int row = idx >> 2;
            int kq = (idx & 3) << 2;
            // A
            float4 av = make_float4(0.f, 0.f, 0.f, 0.f);
            int gr = m0 + row;
            if (gr < nTok) {
                const float* arow;
                if (GATHER)
                    arow = embed + (size_t)(unsigned)(g_keys[gr] & 0xffffffffULL) * ND;
                else
                    arow = g_z + (size_t)gr * ND;
                av = *(const float4*)(arow + k0 + kq);
            }
            As[kq + 0][row] = av.x; As[kq + 1][row] = av.y;
            As[kq + 2][row] = av.z; As[kq + 3][row] = av.w;
            // B
            float4 bv = *(const float4*)(Bsrc + (size_t)(n0 + row) * ND + k0 + kq);
            Bs[kq + 0][row] = bv.x; Bs[kq + 1][row] = bv.y;
            Bs[kq + 2][row] = bv.z; Bs[kq + 3][row] = bv.w;
        }
        __syncthreads();
#pragma unroll
        for (int kk = 0; kk < 16; kk++) {
            float4 a0 = *(const float4*)&As[kk][ty << 2];
            float4 a1 = *(const float4*)&As[kk][64 + (ty << 2)];
            float4 b0 = *(const float4*)&Bs[kk][tx << 2];
            float4 b1 = *(const float4*)&Bs[kk][64 + (tx << 2)];
            float ar[8] = {a0.x, a0.y, a0.z, a0.w, a1.x, a1.y, a1.z, a1.w};
            float br[8] = {b0.x, b0.y, b0.z, b0.w, b1.x, b1.y, b1.z, b1.w};
#pragma unroll
            for (int i = 0; i < 8; i++)
#pragma unroll
                for (int j = 0; j < 8; j++)
                    acc[i][j] = fmaf(ar[i], br[j], acc[i][j]);
        }
        __syncthreads();
    }

    if (ARGMIN) {
#pragma unroll
        for (int i = 0; i < 8; i++) {
            int m = m0 + ((i < 4) ? (ty << 2) + i : 64 + (ty << 2) + i - 4);
            float lb = 3.4e38f; int li = 0x7fffffff;
#pragma unroll
            for (int j = 0; j < 8; j++) {
                int c = n0 + ((j < 4) ? (tx << 2) + j : 64 + (tx << 2) + j - 4);
                float sc = fmaf(-2.f, acc[i][j], g_esq[c]);
                if (sc < lb) { lb = sc; li = c; }
            }
            for (int o = 8; o > 0; o >>= 1) {
                float os = __shfl_xor_sync(0xffffffffu, lb, o);
                int   oi = __shfl_xor_sync(0xffffffffu, li, o);
                if (os < lb || (os == lb && oi < li)) { lb = os; li = oi; }
            }
            if (tx == 0 && m < nTok) {
                unsigned u = __float_as_uint(lb);
                u = (u & 0x80000000u) ? ~u : (u | 0x80000000u);
                unsigned long long key =
                    ((unsigned long long)u << 32) | (unsigned)li;
                atomicMin(&g_keys[m], key);
            }
        }
    } else {
#pragma unroll
        for (int i = 0; i < 8; i++) {
            int m = m0 + ((i < 4) ? (ty << 2) + i : 64 + (ty << 2) + i - 4);
            if (m < nTok) {
                float* crow = g_wq + ((size_t)(tap * nTok + m) << 9);
                float4 v0 = make_float4(acc[i][0], acc[i][1], acc[i][2], acc[i][3]);
                float4 v1 = make_float4(acc[i][4], acc[i][5], acc[i][6], acc[i][7]);
                *(float4*)(crow + n0 + (tx << 2)) = v0;
                *(float4*)(crow + n0 + 64 + (tx << 2)) = v1;
            }
        }
    }
}

// ---------------- fused epilogue: interp(Wq taps) + q_up + Phi mix + updates ----
__global__ void k_phi_ep(const float* __restrict__ embed,
                         const float* __restrict__ bias,
                         int s, float* __restrict__ fhat) {
    int total = NB * NL * 128;
    int nTok = NB * s;
    float ratio = (float)s * (1.0f / 512.0f);
    for (int t = blockIdx.x * blockDim.x + threadIdx.x; t < total;
         t += gridDim.x * blockDim.x) {
        int d4 = t & 127;
        int bl = t >> 7;
        int b = bl >> 9, l = bl & 511;
        const unsigned long long* kb = g_keys + b * s;
        float4 sum = *(const float4*)(bias + (d4 << 2));
        float4 qup = make_float4(0.f, 0.f, 0.f, 0.f);
#pragma unroll
        for (int k = 0; k < 3; k++) {
            int lp = l + k - 1;
            if ((unsigned)lp < 512u) {
                float pos = ((float)lp + 0.5f) * ratio - 0.5f;
                float fl = floorf(pos);
                int i0 = (int)fl;
                float f = pos - fl;
                int ia, ib;
                if (i0 < 0)          { ia = 0;     ib = 0;     f = 0.f; }
                else if (i0 >= s - 1){ ia = s - 1; ib = s - 1; f = 0.f; }
                else                 { ia = i0;    ib = i0 + 1; }
                float w1 = 1.0f - f, w2 = f;
                const float4* wqa = (const float4*)g_wq +
                    (((size_t)(k * nTok + b * s + ia)) << 7) + d4;
                const float4* wqb = (const float4*)g_wq +
                    (((size_t)(k * nTok + b * s + ib)) << 7) + d4;
                float4 va = *wqa, vb = *wqb;
                sum.x += w1 * va.x + w2 * vb.x;
                sum.y += w1 * va.y + w2 * vb.y;
                sum.z += w1 * va.z + w2 * vb.z;
                sum.w += w1 * va.w + w2 * vb.w;
                if (k == 1) {
                    int ca = (int)(unsigned)(kb[ia] & 0xffffffffULL);
                    int cb = (int)(unsigned)(kb[ib] & 0xffffffffULL);
                    float4 ea = *(const float4*)(embed + (size_t)ca * ND + (d4 << 2));
                    float4 eb = *(const float4*)(embed + (size_t)cb * ND + (d4 << 2));
                    qup.x = w1 * ea.x + w2 * eb.x;
                    qup.y = w1 * ea.y + w2 * eb.y;
                    qup.z = w1 * ea.z + w2 * eb.z;
                    qup.w = w1 * ea.w + w2 * eb.w;
                }
            }
        }
        int adr = (bl << 9) + (d4 << 2);
        float4 fh = *(float4*)(fhat + adr);
        float4 rs = *(float4*)(g_resid + adr);
        float v0 = 0.5f * qup.x + 0.5f * sum.x;
        float v1 = 0.5f * qup.y + 0.5f * sum.y;
        float v2 = 0.5f * qup.z + 0.5f * sum.z;
        float v3 = 0.5f * qup.w + 0.5f * sum.w;
        fh.x += v0; fh.y += v1; fh.z += v2; fh.w += v3;
        rs.x -= v0; rs.y -= v1; rs.z -= v2; rs.w -= v3;
        *(float4*)(fhat + adr) = fh;
        *(float4*)(g_resid + adr) = rs;
    }
}

// ---------------- host ----------------
extern "C" void kernel_launch(void* const* d_in, const int* in_sizes, int n_in,
                              void* d_out, int out_size) {
    const float* x     = (const float*)d_in[0];
    const float* embed = (const float*)d_in[1];
    const float* phi_w = (const float*)d_in[2];
    const float* phi_b = (const float*)d_in[3];
    float* out = (float*)d_out;

    // Replicate np.linspace(1/12, 11/12, 4) + first-min tie-break in double.
    double start = 1.0 / 3.0 / 4.0;
    double stop  = 1.0 - 1.0 / 3.0 / 4.0;
    double step  = (stop - start) / 3.0;
    double ticks[4] = { start, start + step, start + 2.0 * step, stop };
    int scales[10] = { 1, 2, 4, 8, 16, 32, 64, 128, 256, 512 };
    int phi_idx[10];
    for (int si = 0; si < 10; si++) {
        double v = (double)si / 9.0;
        int bk = 0; double bd = fabs(ticks[0] - v);
        for (int k = 1; k < 4; k++) {
            double dd = fabs(ticks[k] - v);
            if (dd < bd) { bd = dd; bk = k; }
        }
        phi_idx[si] = bk;
    }

    k_setup_esq<<<512, 256>>>(embed);
    k_setup_wt3<<<1024, 256>>>(phi_w);
    k_init<<<2048, 256>>>(x, out);

    for (int si = 0; si < 10; si++) {
        int s = scales[si];
        int nTok = NB * s;

        if (s <= 16) {
            int segs = (NL / s) / 16;
            int t1 = NB * s * segs * 128;
            int b1 = (t1 + 255) / 256; if (b1 > 2048) b1 = 2048;
            k_down1<<<b1, 256>>>(s, segs);
            int t2 = NB * s * 128;
            int b2 = (t2 + 255) / 256;
            k_down2<<<b2, 256>>>(s, segs);
        } else {
            int total = NB * s * ND;
            int blk = (total + 255) / 256; if (blk > 8192) blk = 8192;
            k_down<<<blk, 256>>>(s);
        }

        int mTiles = (nTok + 127) / 128;
        // quantize: [nTok x 512] @ [4096 x 512]^T with argmin
        k_gemm<false, true><<<dim3(mTiles, NCB / 128), 256>>>(embed, nTok, 0);
        // tap GEMMs: gathered q @ W_tap^T -> g_wq
        k_gemm<true, false><<<dim3(mTiles, ND / 128, 3), 256>>>(embed, nTok, phi_idx[si]);
        // fused interp + Phi + f_hat/residual update
        k_phi_ep<<<4096, 256>>>(embed, phi_b + phi_idx[si] * ND, s, out);
    }
}

// round 4
// speedup vs baseline: 3.7413x; 1.7779x over previous
#include <cuda_runtime.h>
#include <cuda_fp16.h>
#include <math.h>
#include <stdint.h>

#define NB 16
#define NL 512
#define ND 512
#define NCB 4096
#define NTOT (NB*NL*ND)

// ---------------- scratch (device globals, allocation-free) ----------------
__device__ float g_resid[NTOT];                    // 16 MB
__device__ float g_wq[3 * NB * NL * ND];           // 50 MB per-tap q@W^T
__device__ unsigned long long g_keys[NB*NL];
__device__ float g_esq[NCB];
__device__ float g_part[NB*32*ND];
__device__ __half g_embH[NCB*ND], g_embL[NCB*ND];  // split codebook
__device__ __half g_zH[NB*NL*ND], g_zL[NB*NL*ND];  // split downsampled residual
__device__ __half g_wtH[4*3*ND*ND], g_wtL[4*3*ND*ND]; // split weights [p][tap][o][i]

__device__ __forceinline__ void split_h(float x, __half& h, __half& l) {
    h = __float2half_rn(x);
    l = __float2half_rn(x - __half2float(h));
}

// ---------------- setup ----------------
__global__ void k_setup_esq(const float* __restrict__ embed) {
    int gw = (blockIdx.x * blockDim.x + threadIdx.x) >> 5;
    int lane = threadIdx.x & 31;
    if (gw >= NCB) return;
    const float* e = embed + gw * ND;
    float s = 0.f;
    for (int d = lane; d < ND; d += 32) { float v = e[d]; s = fmaf(v, v, s); }
    for (int o = 16; o > 0; o >>= 1) s += __shfl_xor_sync(0xffffffffu, s, o);
    if (lane == 0) g_esq[gw] = s;
}
__global__ void k_split_emb(const float* __restrict__ embed) {
    for (int t = blockIdx.x * blockDim.x + threadIdx.x; t < NCB * ND;
         t += gridDim.x * blockDim.x)
        split_h(embed[t], g_embH[t], g_embL[t]);
}
__global__ void k_setup_wt(const float* __restrict__ phi_w) {
    int total = 4 * 3 * ND * ND;
    for (int t = blockIdx.x * blockDim.x + threadIdx.x; t < total;
         t += gridDim.x * blockDim.x) {
        int i = t & 511;
        int q = t >> 9;
        int o = q & 511; q >>= 9;
        int tap = q % 3;
        int p = q / 3;
        split_h(phi_w[((p * ND + o) * ND + i) * 3 + tap], g_wtH[t], g_wtL[t]);
    }
}
__global__ void k_init(const float* __restrict__ x, float* __restrict__ out) {
    for (int t = blockIdx.x * blockDim.x + threadIdx.x; t < NTOT;
         t += gridDim.x * blockDim.x) {
        g_resid[t] = x[t];
        out[t] = 0.f;
    }
}

// ---------------- downsample (block mean) + split + key reset ----------------
__global__ void k_down(int s) {   // direct, r = NL/s <= 16
    int r = NL / s;
    float inv = 1.0f / (float)r;
    int total = NB * s * ND;
    for (int t = blockIdx.x * blockDim.x + threadIdx.x; t < total;
         t += gridDim.x * blockDim.x) {
        int d = t & 511;
        int bt = t >> 9;
        int b = bt / s, tt = bt % s;
        const float* src = g_resid + (b * NL + tt * r) * ND + d;
        float acc = 0.f;
        for (int j = 0; j < r; j++) acc += src[j * ND];
        acc *= inv;
        split_h(acc, g_zH[t], g_zL[t]);
        if (d == 0) g_keys[bt] = 0xFFFFFFFFFFFFFFFFULL;
    }
}
__global__ void k_down1(int s, int segs) {   // stage 1: sums of 16 rows
    float4* part = (float4*)g_part;
    int total = NB * s * segs * 128;
    for (int t = blockIdx.x * blockDim.x + threadIdx.x; t < total;
         t += gridDim.x * blockDim.x) {
        int d4 = t & 127;
        int rem = t >> 7;
        int seg = rem % segs;
        int bt = rem / segs;
        int b = bt / s, tt = bt % s;
        int r = NL / s;
        const float4* src = (const float4*)(g_resid + (b * NL + tt * r + seg * 16) * ND) + d4;
        float4 a = make_float4(0.f, 0.f, 0.f, 0.f);
        for (int j = 0; j < 16; j++) {
            float4 v = src[j * 128];
            a.x += v.x; a.y += v.y; a.z += v.z; a.w += v.w;
        }
        part[(bt * segs + seg) * 128 + d4] = a;
    }
}
__global__ void k_down2(int s, int segs) {
    const float4* part = (const float4*)g_part;
    float inv = (float)s * (1.0f / (float)NL);
    int total = NB * s * 128;
    for (int t = blockIdx.x * blockDim.x + threadIdx.x; t < total;
         t += gridDim.x * blockDim.x) {
        int d4 = t & 127;
        int bt = t >> 7;
        float4 a = make_float4(0.f, 0.f, 0.f, 0.f);
        for (int sg = 0; sg < segs; sg++) {
            float4 v = part[(bt * segs + sg) * 128 + d4];
            a.x += v.x; a.y += v.y; a.z += v.z; a.w += v.w;
        }
        int base = (bt << 9) + (d4 << 2);
        split_h(a.x * inv, g_zH[base + 0], g_zL[base + 0]);
        split_h(a.y * inv, g_zH[base + 1], g_zL[base + 1]);
        split_h(a.z * inv, g_zH[base + 2], g_zL[base + 2]);
        split_h(a.w * inv, g_zH[base + 3], g_zL[base + 3]);
        if (d4 == 0) g_keys[bt] = 0xFFFFFFFFFFFFFFFFULL;
    }
}

// ---------------- mma.sync fp16x3 GEMM: 128x128 tile, 8 warps (m64 x n32) ----
#define MMA16816(d, a, b0, b1) \
    asm volatile("mma.sync.aligned.m16n8k16.row.col.f32.f16.f16.f32 " \
        "{%0,%1,%2,%3}, {%4,%5,%6,%7}, {%8,%9}, {%0,%1,%2,%3};" \
        : "+f"((d)[0]), "+f"((d)[1]), "+f"((d)[2]), "+f"((d)[3]) \
        : "r"((a)[0]), "r"((a)[1]), "r"((a)[2]), "r"((a)[3]), "r"(b0), "r"(b1))

template<bool GATHER, bool ARGMIN>
__global__ __launch_bounds__(256, 2) void k_gemm_h(int nTok, int p) {
    // smem tiles: [128 rows][k16] halves, padded to 24 halfs (12 half2) per row
    __shared__ __align__(16) __half sAh[128*24], sAl[128*24];
    __shared__ __align__(16) __half sBh[128*24], sBl[128*24];
    int tid = threadIdx.x;
    int lane = tid & 31, wid = tid >> 5;
    int wm = wid >> 2, wn = wid & 3;           // warp tile: m64 x n32
    int gr4 = lane >> 2, gc4 = lane & 3;
    int m0 = blockIdx.x * 128, n0 = blockIdx.y * 128;
    int tap = blockIdx.z;

    const __half* AH; const __half* ALo;
    const __half* BH; const __half* BL;
    if (ARGMIN) { AH = g_zH; ALo = g_zL; BH = g_embH; BL = g_embL; }
    else {
        AH = g_embH; ALo = g_embL;
        size_t wo = (size_t)(p * 3 + tap) * (ND * ND);
        BH = g_wtH + wo; BL = g_wtL + wo;
    }

    // per-thread load mapping: row = tid>>1 (0..127), part = tid&1 (which 16B)
    int lrow = tid >> 1, part = tid & 1;
    int gm = m0 + lrow;
    bool avalid = (gm < nTok);
    size_t aoff = 0;
    if (avalid) {
        if (GATHER) aoff = (size_t)(unsigned)(g_keys[gm] & 0xffffffffULL) * ND;
        else        aoff = (size_t)gm * ND;
    }
    size_t boff = (size_t)(n0 + lrow) * ND;
    int soff = lrow * 24 + part * 8;           // half index in smem

    float acc[4][4][4];
#pragma unroll
    for (int i = 0; i < 4; i++)
#pragma unroll
        for (int j = 0; j < 4; j++)
#pragma unroll
            for (int q = 0; q < 4; q++) acc[i][j][q] = 0.f;

    const uint4 z4 = make_uint4(0, 0, 0, 0);
    for (int kb = 0; kb < 32; kb++) {
        int k0 = kb * 16 + part * 8;
        uint4 vah = z4, valo = z4;
        if (avalid) {
            vah  = *(const uint4*)(AH  + aoff + k0);
            valo = *(const uint4*)(ALo + aoff + k0);
        }
        uint4 vbh = *(const uint4*)(BH + boff + k0);
        uint4 vbl = *(const uint4*)(BL + boff + k0);
        __syncthreads();
        *(uint4*)(sAh + soff) = vah;
        *(uint4*)(sAl + soff) = valo;
        *(uint4*)(sBh + soff) = vbh;
        *(uint4*)(sBl + soff) = vbl;
        __syncthreads();

        const uint32_t* A2h = (const uint32_t*)sAh;
        const uint32_t* A2l = (const uint32_t*)sAl;
        const uint32_t* B2h = (const uint32_t*)sBh;
        const uint32_t* B2l = (const uint32_t*)sBl;

        uint32_t ah[4][4], al[4][4];
#pragma unroll
        for (int mt = 0; mt < 4; mt++) {
            int r0 = (wm * 64 + mt * 16 + gr4) * 12 + gc4;
            int r1 = r0 + 8 * 12;
            ah[mt][0] = A2h[r0];     ah[mt][1] = A2h[r1];
            ah[mt][2] = A2h[r0 + 4]; ah[mt][3] = A2h[r1 + 4];
            al[mt][0] = A2l[r0];     al[mt][1] = A2l[r1];
            al[mt][2] = A2l[r0 + 4]; al[mt][3] = A2l[r1 + 4];
        }
#pragma unroll
        for (int nt = 0; nt < 4; nt++) {
            int c0 = (wn * 32 + nt * 8 + gr4) * 12 + gc4;
            uint32_t bh0 = B2h[c0], bh1 = B2h[c0 + 4];
            uint32_t bl0 = B2l[c0], bl1 = B2l[c0 + 4];
#pragma unroll
            for (int mt = 0; mt < 4; mt++) {
                MMA16816(acc[mt][nt], ah[mt], bh0, bh1);
                MMA16816(acc[mt][nt], al[mt], bh0, bh1);
                MMA16816(acc[mt][nt], ah[mt], bl0, bl1);
            }
        }
    }

    if (ARGMIN) {
#pragma unroll
        for (int mt = 0; mt < 4; mt++) {
#pragma unroll
            for (int h = 0; h < 2; h++) {
                int m = m0 + wm * 64 + mt * 16 + gr4 + 8 * h;
                float lb = 3.4e38f; int li = 0x7fffffff;
#pragma unroll
                for (int nt = 0; nt < 4; nt++) {
                    int c = n0 + wn * 32 + nt * 8 + 2 * gc4;
                    float s0 = fmaf(-2.f, acc[mt][nt][2 * h],     __ldg(&g_esq[c]));
                    float s1 = fmaf(-2.f, acc[mt][nt][2 * h + 1], __ldg(&g_esq[c + 1]));
                    if (s0 < lb) { lb = s0; li = c; }
                    if (s1 < lb) { lb = s1; li = c + 1; }
                }
                // reduce across the 4 lanes owning this row (lane^1, lane^2)
#pragma unroll
                for (int o = 1; o <= 2; o <<= 1) {
                    float os = __shfl_xor_sync(0xffffffffu, lb, o);
                    int   oi = __shfl_xor_sync(0xffffffffu, li, o);
                    if (os < lb || (os == lb && oi < li)) { lb = os; li = oi; }
                }
                if (gc4 == 0 && m < nTok) {
                    unsigned u = __float_as_uint(lb);
                    u = (u & 0x80000000u) ? ~u : (u | 0x80000000u);
                    unsigned long long key =
                        ((unsigned long long)u << 32) | (unsigned)li;
                    atomicMin(&g_keys[m], key);
                }
            }
        }
    } else {
#pragma unroll
        for (int mt = 0; mt < 4; mt++) {
#pragma unroll
            for (int h = 0; h < 2; h++) {
                int m = m0 + wm * 64 + mt * 16 + gr4 + 8 * h;
                if (m < nTok) {
                    float* crow = g_wq + ((size_t)(tap * nTok + m) << 9);
#pragma unroll
                    for (int nt = 0; nt < 4; nt++) {
                        int c = n0 + wn * 32 + nt * 8 + 2 * gc4;
                        *(float2*)(crow + c) =
                            make_float2(acc[mt][nt][2 * h], acc[mt][nt][2 * h + 1]);
                    }
                }
            }
        }
    }
}

// ---------------- fused epilogue: interp(Wq taps) + q_up + Phi mix + updates ----
__global__ void k_phi_ep(const float* __restrict__ embed,
                         const float* __restrict__ bias,
                         int s, float* __restrict__ fhat) {
    int total = NB * NL * 128;
    int nTok = NB * s;
    float ratio = (float)s * (1.0f / 512.0f);
    for (int t = blockIdx.x * blockDim.x + threadIdx.x; t < total;
         t += gridDim.x * blockDim.x) {
        int d4 = t & 127;
        int bl = t >> 7;
        int b = bl >> 9, l = bl & 511;
        const unsigned long long* kb = g_keys + b * s;
        float4 sum = *(const float4*)(bias + (d4 << 2));
        float4 qup = make_float4(0.f, 0.f, 0.f, 0.f);
#pragma unroll
        for (int k = 0; k < 3; k++) {
            int lp = l + k - 1;
            if ((unsigned)lp < 512u) {
                float pos = ((float)lp + 0.5f) * ratio - 0.5f;
                float fl = floorf(pos);
                int i0 = (int)fl;
                float f = pos - fl;
                int ia, ib;
                if (i0 < 0)          { ia = 0;     ib = 0;     f = 0.f; }
                else if (i0 >= s - 1){ ia = s - 1; ib = s - 1; f = 0.f; }
                else                 { ia = i0;    ib = i0 + 1; }
                float w1 = 1.0f - f, w2 = f;
                const float4* wqa = (const float4*)g_wq +
                    (((size_t)(k * nTok + b * s + ia)) << 7) + d4;
                const float4* wqb = (const float4*)g_wq +
                    (((size_t)(k * nTok + b * s + ib)) << 7) + d4;
                float4 va = *wqa, vb = *wqb;
                sum.x += w1 * va.x + w2 * vb.x;
                sum.y += w1 * va.y + w2 * vb.y;
                sum.z += w1 * va.z + w2 * vb.z;
                sum.w += w1 * va.w + w2 * vb.w;
                if (k == 1) {
                    int ca = (int)(unsigned)(kb[ia] & 0xffffffffULL);
                    int cb = (int)(unsigned)(kb[ib] & 0xffffffffULL);
                    float4 ea = *(const float4*)(embed + (size_t)ca * ND + (d4 << 2));
                    float4 eb = *(const float4*)(embed + (size_t)cb * ND + (d4 << 2));
                    qup.x = w1 * ea.x + w2 * eb.x;
                    qup.y = w1 * ea.y + w2 * eb.y;
                    qup.z = w1 * ea.z + w2 * eb.z;
                    qup.w = w1 * ea.w + w2 * eb.w;
                }
            }
        }
        int adr = (bl << 9) + (d4 << 2);
        float4 fh = *(float4*)(fhat + adr);
        float4 rs = *(float4*)(g_resid + adr);
        float v0 = 0.5f * qup.x + 0.5f * sum.x;
        float v1 = 0.5f * qup.y + 0.5f * sum.y;
        float v2 = 0.5f * qup.z + 0.5f * sum.z;
        float v3 = 0.5f * qup.w + 0.5f * sum.w;
        fh.x += v0; fh.y += v1; fh.z += v2; fh.w += v3;
        rs.x -= v0; rs.y -= v1; rs.z -= v2; rs.w -= v3;
        *(float4*)(fhat + adr) = fh;
        *(float4*)(g_resid + adr) = rs;
    }
}

// ---------------- host ----------------
extern "C" void kernel_launch(void* const* d_in, const int* in_sizes, int n_in,
                              void* d_out, int out_size) {
    const float* x     = (const float*)d_in[0];
    const float* embed = (const float*)d_in[1];
    const float* phi_w = (const float*)d_in[2];
    const float* phi_b = (const float*)d_in[3];
    float* out = (float*)d_out;

    // Replicate np.linspace(1/12, 11/12, 4) + first-min tie-break in double.
    double start = 1.0 / 3.0 / 4.0;
    double stop  = 1.0 - 1.0 / 3.0 / 4.0;
    double step  = (stop - start) / 3.0;
    double ticks[4] = { start, start + step, start + 2.0 * step, stop };
    int scales[10] = { 1, 2, 4, 8, 16, 32, 64, 128, 256, 512 };
    int phi_idx[10];
    for (int si = 0; si < 10; si++) {
        double v = (double)si / 9.0;
        int bk = 0; double bd = fabs(ticks[0] - v);
        for (int k = 1; k < 4; k++) {
            double dd = fabs(ticks[k] - v);
            if (dd < bd) { bd = dd; bk = k; }
        }
        phi_idx[si] = bk;
    }

    k_setup_esq<<<512, 256>>>(embed);
    k_split_emb<<<1024, 256>>>(embed);
    k_setup_wt<<<1024, 256>>>(phi_w);
    k_init<<<2048, 256>>>(x, out);

    for (int si = 0; si < 10; si++) {
        int s = scales[si];
        int nTok = NB * s;

        if (s <= 16) {
            int segs = (NL / s) / 16;
            int t1 = NB * s * segs * 128;
            int b1 = (t1 + 255) / 256; if (b1 > 2048) b1 = 2048;
            k_down1<<<b1, 256>>>(s, segs);
            int t2 = NB * s * 128;
            int b2 = (t2 + 255) / 256;
            k_down2<<<b2, 256>>>(s, segs);
        } else {
            int total = NB * s * ND;
            int blk = (total + 255) / 256; if (blk > 8192) blk = 8192;
            k_down<<<blk, 256>>>(s);
        }

        int mTiles = (nTok + 127) / 128;
        // quantize: [nTok x 512] @ [4096 x 512]^T with fused argmin
        k_gemm_h<false, true><<<dim3(mTiles, NCB / 128), 256>>>(nTok, 0);
        // tap GEMMs: gathered q @ W_tap^T -> g_wq
        k_gemm_h<true, false><<<dim3(mTiles, ND / 128, 3), 256>>>(nTok, phi_idx[si]);
        // fused interp + Phi + f_hat/residual update
        k_phi_ep<<<4096, 256>>>(embed, phi_b + phi_idx[si] * ND, s, out);
    }
}

// round 5
// speedup vs baseline: 3.9844x; 1.0650x over previous
#include <cuda_runtime.h>
#include <cuda_fp16.h>
#include <math.h>
#include <stdint.h>

#define NB 16
#define NL 512
#define ND 512
#define NCB 4096
#define NTOT (NB*NL*ND)

// ---------------- scratch (device globals, allocation-free) ----------------
__device__ float g_resid[NTOT];
__device__ float g_wq[3 * NB * NL * ND];
__device__ unsigned long long g_keys[NB*NL];
__device__ float g_esq[NCB];
__device__ float g_part[NB*32*ND];
__device__ __half g_embH[NCB*ND], g_embL[NCB*ND];
__device__ __half g_zH[NB*NL*ND], g_zL[NB*NL*ND];
__device__ __half g_wtH[4*3*ND*ND], g_wtL[4*3*ND*ND];

__device__ __forceinline__ void split_h(float x, __half& h, __half& l) {
    h = __float2half_rn(x);
    l = __float2half_rn(x - __half2float(h));
}

// ---------------- setup ----------------
__global__ void k_setup_esq(const float* __restrict__ embed) {
    int gw = (blockIdx.x * blockDim.x + threadIdx.x) >> 5;
    int lane = threadIdx.x & 31;
    if (gw >= NCB) return;
    const float* e = embed + gw * ND;
    float s = 0.f;
    for (int d = lane; d < ND; d += 32) { float v = e[d]; s = fmaf(v, v, s); }
    for (int o = 16; o > 0; o >>= 1) s += __shfl_xor_sync(0xffffffffu, s, o);
    if (lane == 0) g_esq[gw] = s;
}
__global__ void k_split_emb(const float* __restrict__ embed) {
    for (int t = blockIdx.x * blockDim.x + threadIdx.x; t < NCB * ND;
         t += gridDim.x * blockDim.x)
        split_h(embed[t], g_embH[t], g_embL[t]);
}
__global__ void k_setup_wt(const float* __restrict__ phi_w) {
    int total = 4 * 3 * ND * ND;
    for (int t = blockIdx.x * blockDim.x + threadIdx.x; t < total;
         t += gridDim.x * blockDim.x) {
        int i = t & 511;
        int q = t >> 9;
        int o = q & 511; q >>= 9;
        int tap = q % 3;
        int p = q / 3;
        split_h(phi_w[((p * ND + o) * ND + i) * 3 + tap], g_wtH[t], g_wtL[t]);
    }
}
__global__ void k_init(const float* __restrict__ x, float* __restrict__ out) {
    for (int t = blockIdx.x * blockDim.x + threadIdx.x; t < NTOT;
         t += gridDim.x * blockDim.x) {
        g_resid[t] = x[t];
        out[t] = 0.f;
    }
}

// ---------------- downsample (block mean) + split + key reset ----------------
__global__ void k_down(int s) {   // direct, r = NL/s <= 16
    int r = NL / s;
    float inv = 1.0f / (float)r;
    int total = NB * s * ND;
    for (int t = blockIdx.x * blockDim.x + threadIdx.x; t < total;
         t += gridDim.x * blockDim.x) {
        int d = t & 511;
        int bt = t >> 9;
        int b = bt / s, tt = bt % s;
        const float* src = g_resid + (b * NL + tt * r) * ND + d;
        float acc = 0.f;
        for (int j = 0; j < r; j++) acc += src[j * ND];
        acc *= inv;
        split_h(acc, g_zH[t], g_zL[t]);
        if (d == 0) g_keys[bt] = 0xFFFFFFFFFFFFFFFFULL;
    }
}
__global__ void k_down1(int s, int segs) {
    float4* part = (float4*)g_part;
    int total = NB * s * segs * 128;
    for (int t = blockIdx.x * blockDim.x + threadIdx.x; t < total;
         t += gridDim.x * blockDim.x) {
        int d4 = t & 127;
        int rem = t >> 7;
        int seg = rem % segs;
        int bt = rem / segs;
        int b = bt / s, tt = bt % s;
        int r = NL / s;
        const float4* src = (const float4*)(g_resid + (b * NL + tt * r + seg * 16) * ND) + d4;
        float4 a = make_float4(0.f, 0.f, 0.f, 0.f);
        for (int j = 0; j < 16; j++) {
            float4 v = src[j * 128];
            a.x += v.x; a.y += v.y; a.z += v.z; a.w += v.w;
        }
        part[(bt * segs + seg) * 128 + d4] = a;
    }
}
__global__ void k_down2(int s, int segs) {
    const float4* part = (const float4*)g_part;
    float inv = (float)s * (1.0f / (float)NL);
    int total = NB * s * 128;
    for (int t = blockIdx.x * blockDim.x + threadIdx.x; t < total;
         t += gridDim.x * blockDim.x) {
        int d4 = t & 127;
        int bt = t >> 7;
        float4 a = make_float4(0.f, 0.f, 0.f, 0.f);
        for (int sg = 0; sg < segs; sg++) {
            float4 v = part[(bt * segs + sg) * 128 + d4];
            a.x += v.x; a.y += v.y; a.z += v.z; a.w += v.w;
        }
        int base = (bt << 9) + (d4 << 2);
        split_h(a.x * inv, g_zH[base + 0], g_zL[base + 0]);
        split_h(a.y * inv, g_zH[base + 1], g_zL[base + 1]);
        split_h(a.z * inv, g_zH[base + 2], g_zL[base + 2]);
        split_h(a.w * inv, g_zH[base + 3], g_zL[base + 3]);
        if (d4 == 0) g_keys[bt] = 0xFFFFFFFFFFFFFFFFULL;
    }
}

// ---------------- async-pipelined mma.sync fp16x3 GEMM ----------------
// smem stage layout (bytes): Ah[0,10240) Al[10240,20480) Bh[20480,30720) Bl[30720,40960)
// rows padded to 40 halves (80 B) -> conflict-free ldmatrix (20-bank row stride)
#define STAGE_B 40960
#define PITCH_B 80

#define MMA16816(d, a, b0, b1) \
    asm volatile("mma.sync.aligned.m16n8k16.row.col.f32.f16.f16.f32 " \
        "{%0,%1,%2,%3}, {%4,%5,%6,%7}, {%8,%9}, {%0,%1,%2,%3};" \
        : "+f"((d)[0]), "+f"((d)[1]), "+f"((d)[2]), "+f"((d)[3]) \
        : "r"((a)[0]), "r"((a)[1]), "r"((a)[2]), "r"((a)[3]), "r"(b0), "r"(b1))

__device__ __forceinline__ uint32_t smem_u32(const void* p) {
    uint32_t a;
    asm("{ .reg .u64 t; cvta.to.shared.u64 t, %1; cvt.u32.u64 %0, t; }" : "=r"(a) : "l"(p));
    return a;
}
__device__ __forceinline__ void cp16(uint32_t s, const void* g, int sz) {
    asm volatile("cp.async.cg.shared.global [%0], [%1], 16, %2;"
        :: "r"(s), "l"(g), "r"(sz) : "memory");
}
#define CP_COMMIT() asm volatile("cp.async.commit_group;" ::: "memory")
#define CP_WAIT1()  asm volatile("cp.async.wait_group 1;" ::: "memory")
#define CP_WAIT0()  asm volatile("cp.async.wait_group 0;" ::: "memory")
__device__ __forceinline__ void ldsm4(uint32_t* r, uint32_t addr) {
    asm volatile("ldmatrix.sync.aligned.m8n8.x4.shared.b16 {%0,%1,%2,%3}, [%4];"
        : "=r"(r[0]), "=r"(r[1]), "=r"(r[2]), "=r"(r[3]) : "r"(addr));
}

template<bool GATHER, bool ARGMIN>
__global__ __launch_bounds__(256, 2) void k_gemm_h(int nTok, int p) {
    extern __shared__ __align__(16) char dsm[];
    uint32_t sbase = smem_u32(dsm);
    int tid = threadIdx.x;
    int lane = tid & 31, wid = tid >> 5;
    int wm = wid >> 2, wn = wid & 3;           // warp tile m64 x n32
    int gr4 = lane >> 2, gc4 = lane & 3;
    int m0 = blockIdx.x * 128, n0 = blockIdx.y * 128;
    int tap = blockIdx.z;

    const __half* AH; const __half* ALo;
    const __half* BH; const __half* BL;
    if (ARGMIN) { AH = g_zH; ALo = g_zL; BH = g_embH; BL = g_embL; }
    else {
        AH = g_embH; ALo = g_embL;
        size_t wo = (size_t)(p * 3 + tap) * (ND * ND);
        BH = g_wtH + wo; BL = g_wtL + wo;
    }

    // per-thread cp.async mapping: row = tid>>1, 2 chunks of 16B at (tid&1)*32B
    int lrow = tid >> 1;
    int gm = m0 + lrow;
    bool avalid = (gm < nTok);
    int asz = avalid ? 16 : 0;
    size_t aoff = 0;
    if (avalid) {
        if (GATHER) aoff = (size_t)(unsigned)(g_keys[gm] & 0xffffffffULL) * ND;
        else        aoff = (size_t)gm * ND;
    }
    size_t boff = (size_t)(n0 + lrow) * ND;
    int cByte = (tid & 1) * 32;                 // byte offset of first chunk in k-row
    const char* gAh = (const char*)(AH  + aoff) + cByte;
    const char* gAl = (const char*)(ALo + aoff) + cByte;
    const char* gBh = (const char*)(BH  + boff) + cByte;
    const char* gBl = (const char*)(BL  + boff) + cByte;
    uint32_t sOff = sbase + lrow * PITCH_B + cByte;

    // fragment ldmatrix bases
    int lm = lane & 15, lk = lane >> 4;
    uint32_t aFrag = sbase + (wm * 64 + lm) * PITCH_B + lk * 16;          // Ah
    uint32_t bFrag = sbase + 20480 + (wn * 32 + lm) * PITCH_B + lk * 16;  // Bh

    float acc[4][4][4];
#pragma unroll
    for (int i = 0; i < 4; i++)
#pragma unroll
        for (int j = 0; j < 4; j++)
#pragma unroll
            for (int q = 0; q < 4; q++) acc[i][j][q] = 0.f;

#define ISSUE(stg, kb) do { \
        uint32_t so = sOff + (stg) * STAGE_B; \
        int gb = (kb) * 64; \
        cp16(so,              gAh + gb,      asz); \
        cp16(so + 16,         gAh + gb + 16, asz); \
        cp16(so + 10240,      gAl + gb,      asz); \
        cp16(so + 10240 + 16, gAl + gb + 16, asz); \
        cp16(so + 20480,      gBh + gb,      16); \
        cp16(so + 20480 + 16, gBh + gb + 16, 16); \
        cp16(so + 30720,      gBl + gb,      16); \
        cp16(so + 30720 + 16, gBl + gb + 16, 16); \
        CP_COMMIT(); \
    } while (0)

    ISSUE(0, 0);
    const int C = ND / 32;   // 16 k-blocks
    for (int kb = 0; kb < C; kb++) {
        int st = kb & 1;
        __syncthreads();                       // protect next buffer from overwrite
        if (kb + 1 < C) { ISSUE((kb + 1) & 1, kb + 1); CP_WAIT1(); }
        else            { CP_WAIT0(); }
        __syncthreads();                       // stage st data visible to all

        uint32_t sa = (uint32_t)st * STAGE_B;
#pragma unroll
        for (int kp = 0; kp < 2; kp++) {
            uint32_t ah[4][4], al[4][4];
#pragma unroll
            for (int mt = 0; mt < 4; mt++) {
                uint32_t adr = aFrag + sa + mt * (16 * PITCH_B) + kp * 32;
                ldsm4(ah[mt], adr);
                ldsm4(al[mt], adr + 10240);
            }
#pragma unroll
            for (int ntp = 0; ntp < 2; ntp++) {
                uint32_t bh[4], bl[4];
                uint32_t badr = bFrag + sa + ntp * (16 * PITCH_B) + kp * 32;
                ldsm4(bh, badr);
                ldsm4(bl, badr + 10240);
#pragma unroll
                for (int mt = 0; mt < 4; mt++) {
                    MMA16816(acc[mt][2 * ntp],     ah[mt], bh[0], bh[2]);
                    MMA16816(acc[mt][2 * ntp],     al[mt], bh[0], bh[2]);
                    MMA16816(acc[mt][2 * ntp],     ah[mt], bl[0], bl[2]);
                    MMA16816(acc[mt][2 * ntp + 1], ah[mt], bh[1], bh[3]);
                    MMA16816(acc[mt][2 * ntp + 1], al[mt], bh[1], bh[3]);
                    MMA16816(acc[mt][2 * ntp + 1], ah[mt], bl[1], bl[3]);
                }
            }
        }
    }
#undef ISSUE

    if (ARGMIN) {
#pragma unroll
        for (int mt = 0; mt < 4; mt++) {
#pragma unroll
            for (int h = 0; h < 2; h++) {
                int m = m0 + wm * 64 + mt * 16 + gr4 + 8 * h;
                float lb = 3.4e38f; int li = 0x7fffffff;
#pragma unroll
                for (int nt = 0; nt < 4; nt++) {
                    int c = n0 + wn * 32 + nt * 8 + 2 * gc4;
                    float s0 = fmaf(-2.f, acc[mt][nt][2 * h],     __ldg(&g_esq[c]));
                    float s1 = fmaf(-2.f, acc[mt][nt][2 * h + 1], __ldg(&g_esq[c + 1]));
                    if (s0 < lb) { lb = s0; li = c; }
                    if (s1 < lb) { lb = s1; li = c + 1; }
                }
#pragma unroll
                for (int o = 1; o <= 2; o <<= 1) {
                    float os = __shfl_xor_sync(0xffffffffu, lb, o);
                    int   oi = __shfl_xor_sync(0xffffffffu, li, o);
                    if (os < lb || (os == lb && oi < li)) { lb = os; li = oi; }
                }
                if (gc4 == 0 && m < nTok) {
                    unsigned u = __float_as_uint(lb);
                    u = (u & 0x80000000u) ? ~u : (u | 0x80000000u);
                    unsigned long long key =
                        ((unsigned long long)u << 32) | (unsigned)li;
                    atomicMin(&g_keys[m], key);
                }
            }
        }
    } else {
#pragma unroll
        for (int mt = 0; mt < 4; mt++) {
#pragma unroll
            for (int h = 0; h < 2; h++) {
                int m = m0 + wm * 64 + mt * 16 + gr4 + 8 * h;
                if (m < nTok) {
                    float* crow = g_wq + ((size_t)(tap * nTok + m) << 9);
#pragma unroll
                    for (int nt = 0; nt < 4; nt++) {
                        int c = n0 + wn * 32 + nt * 8 + 2 * gc4;
                        *(float2*)(crow + c) =
                            make_float2(acc[mt][nt][2 * h], acc[mt][nt][2 * h + 1]);
                    }
                }
            }
        }
    }
}

// ---------------- fused epilogue: interp(Wq taps) + q_up + Phi mix + updates ----
__global__ void k_phi_ep(const float* __restrict__ embed,
                         const float* __restrict__ bias,
                         int s, float* __restrict__ fhat) {
    int total = NB * NL * 128;
    int nTok = NB * s;
    float ratio = (float)s * (1.0f / 512.0f);
    for (int t = blockIdx.x * blockDim.x + threadIdx.x; t < total;
         t += gridDim.x * blockDim.x) {
        int d4 = t & 127;
        int bl = t >> 7;
        int b = bl >> 9, l = bl & 511;
        const unsigned long long* kb = g_keys + b * s;
        float4 sum = *(const float4*)(bias + (d4 << 2));
        float4 qup = make_float4(0.f, 0.f, 0.f, 0.f);
#pragma unroll
        for (int k = 0; k < 3; k++) {
            int lp = l + k - 1;
            if ((unsigned)lp < 512u) {
                float pos = ((float)lp + 0.5f) * ratio - 0.5f;
                float fl = floorf(pos);
                int i0 = (int)fl;
                float f = pos - fl;
                int ia, ib;
                if (i0 < 0)          { ia = 0;     ib = 0;     f = 0.f; }
                else if (i0 >= s - 1){ ia = s - 1; ib = s - 1; f = 0.f; }
                else                 { ia = i0;    ib = i0 + 1; }
                float w1 = 1.0f - f, w2 = f;
                const float4* wqa = (const float4*)g_wq +
                    (((size_t)(k * nTok + b * s + ia)) << 7) + d4;
                const float4* wqb = (const float4*)g_wq +
                    (((size_t)(k * nTok + b * s + ib)) << 7) + d4;
                float4 va = *wqa, vb = *wqb;
                sum.x += w1 * va.x + w2 * vb.x;
                sum.y += w1 * va.y + w2 * vb.y;
                sum.z += w1 * va.z + w2 * vb.z;
                sum.w += w1 * va.w + w2 * vb.w;
                if (k == 1) {
                    int ca = (int)(unsigned)(kb[ia] & 0xffffffffULL);
                    int cb = (int)(unsigned)(kb[ib] & 0xffffffffULL);
                    float4 ea = *(const float4*)(embed + (size_t)ca * ND + (d4 << 2));
                    float4 eb = *(const float4*)(embed + (size_t)cb * ND + (d4 << 2));
                    qup.x = w1 * ea.x + w2 * eb.x;
                    qup.y = w1 * ea.y + w2 * eb.y;
                    qup.z = w1 * ea.z + w2 * eb.z;
                    qup.w = w1 * ea.w + w2 * eb.w;
                }
            }
        }
        int adr = (bl << 9) + (d4 << 2);
        float4 fh = *(float4*)(fhat + adr);
        float4 rs = *(float4*)(g_resid + adr);
        float v0 = 0.5f * qup.x + 0.5f * sum.x;
        float v1 = 0.5f * qup.y + 0.5f * sum.y;
        float v2 = 0.5f * qup.z + 0.5f * sum.z;
        float v3 = 0.5f * qup.w + 0.5f * sum.w;
        fh.x += v0; fh.y += v1; fh.z += v2; fh.w += v3;
        rs.x -= v0; rs.y -= v1; rs.z -= v2; rs.w -= v3;
        *(float4*)(fhat + adr) = fh;
        *(float4*)(g_resid + adr) = rs;
    }
}

// ---------------- host ----------------
extern "C" void kernel_launch(void* const* d_in, const int* in_sizes, int n_in,
                              void* d_out, int out_size) {
    const float* x     = (const float*)d_in[0];
    const float* embed = (const float*)d_in[1];
    const float* phi_w = (const float*)d_in[2];
    const float* phi_b = (const float*)d_in[3];
    float* out = (float*)d_out;

    const int DSMB = 2 * STAGE_B;   // 80 KB
    cudaFuncSetAttribute(k_gemm_h<false, true>,
                         cudaFuncAttributeMaxDynamicSharedMemorySize, DSMB);
    cudaFuncSetAttribute(k_gemm_h<true, false>,
                         cudaFuncAttributeMaxDynamicSharedMemorySize, DSMB);

    // Replicate np.linspace(1/12, 11/12, 4) + first-min tie-break in double.
    double start = 1.0 / 3.0 / 4.0;
    double stop  = 1.0 - 1.0 / 3.0 / 4.0;
    double step  = (stop - start) / 3.0;
    double ticks[4] = { start, start + step, start + 2.0 * step, stop };
    int scales[10] = { 1, 2, 4, 8, 16, 32, 64, 128, 256, 512 };
    int phi_idx[10];
    for (int si = 0; si < 10; si++) {
        double v = (double)si / 9.0;
        int bk = 0; double bd = fabs(ticks[0] - v);
        for (int k = 1; k < 4; k++) {
            double dd = fabs(ticks[k] - v);
            if (dd < bd) { bd = dd; bk = k; }
        }
        phi_idx[si] = bk;
    }

    k_setup_esq<<<512, 256>>>(embed);
    k_split_emb<<<1024, 256>>>(embed);
    k_setup_wt<<<1024, 256>>>(phi_w);
    k_init<<<2048, 256>>>(x, out);

    for (int si = 0; si < 10; si++) {
        int s = scales[si];
        int nTok = NB * s;

        if (s <= 16) {
            int segs = (NL / s) / 16;
            int t1 = NB * s * segs * 128;
            int b1 = (t1 + 255) / 256; if (b1 > 2048) b1 = 2048;
            k_down1<<<b1, 256>>>(s, segs);
            int t2 = NB * s * 128;
            int b2 = (t2 + 255) / 256;
            k_down2<<<b2, 256>>>(s, segs);
        } else {
            int total = NB * s * ND;
            int blk = (total + 255) / 256; if (blk > 8192) blk = 8192;
            k_down<<<blk, 256>>>(s);
        }

        int mTiles = (nTok + 127) / 128;
        k_gemm_h<false, true><<<dim3(mTiles, NCB / 128), 256, DSMB>>>(nTok, 0);
        k_gemm_h<true, false><<<dim3(mTiles, ND / 128, 3), 256, DSMB>>>(nTok, phi_idx[si]);
        k_phi_ep<<<4096, 256>>>(embed, phi_b + phi_idx[si] * ND, s, out);
    }
}

// round 7
// speedup vs baseline: 4.8242x; 1.2108x over previous
#include <cuda_runtime.h>
#include <cuda_fp16.h>
#include <math.h>
#include <stdint.h>

#define NB 16
#define NL 512
#define ND 512
#define NCB 4096
#define NTOT (NB*NL*ND)

// ---------------- scratch (device globals, allocation-free) ----------------
__device__ float g_resid[NTOT];
__device__ float g_tapw[12 * NCB * ND];          // 100 MB: [(p*3+tap)][code][o]
__device__ unsigned long long g_keys[NB*NL];     // final code index per token
__device__ unsigned g_cand[NB*NL*64];            // top-2 per 128-block, 32 blocks
__device__ float g_esq[NCB];
__device__ float g_part[NB*32*ND];
__device__ __half g_embH[NCB*ND], g_embL[NCB*ND];
__device__ __half g_zH[NB*NL*ND], g_zL[NB*NL*ND];
__device__ __half g_wtH[4*3*ND*ND], g_wtL[4*3*ND*ND];  // [p][tap][o][i]

__device__ __forceinline__ void split_h(float x, __half& h, __half& l) {
    h = __float2half_rn(x);
    l = __float2half_rn(x - __half2float(h));
}

// ---------------- setup ----------------
__global__ void k_setup_esq(const float* __restrict__ embed) {
    int gw = (blockIdx.x * blockDim.x + threadIdx.x) >> 5;
    int lane = threadIdx.x & 31;
    if (gw >= NCB) return;
    const float* e = embed + gw * ND;
    float s = 0.f;
    for (int d = lane; d < ND; d += 32) { float v = e[d]; s = fmaf(v, v, s); }
    for (int o = 16; o > 0; o >>= 1) s += __shfl_xor_sync(0xffffffffu, s, o);
    if (lane == 0) g_esq[gw] = s;
}
__global__ void k_split_emb(const float* __restrict__ embed) {
    for (int t = blockIdx.x * blockDim.x + threadIdx.x; t < NCB * ND;
         t += gridDim.x * blockDim.x)
        split_h(embed[t], g_embH[t], g_embL[t]);
}
__global__ void k_setup_wt(const float* __restrict__ phi_w) {
    int total = 4 * 3 * ND * ND;
    for (int t = blockIdx.x * blockDim.x + threadIdx.x; t < total;
         t += gridDim.x * blockDim.x) {
        int i = t & 511;
        int q = t >> 9;
        int o = q & 511; q >>= 9;
        int tap = q % 3;
        int p = q / 3;
        split_h(phi_w[((p * ND + o) * ND + i) * 3 + tap], g_wtH[t], g_wtL[t]);
    }
}
__global__ void k_init(const float* __restrict__ x, float* __restrict__ out) {
    for (int t = blockIdx.x * blockDim.x + threadIdx.x; t < NTOT;
         t += gridDim.x * blockDim.x) {
        g_resid[t] = x[t];
        out[t] = 0.f;
    }
}

// ---------------- downsample (block mean) + split ----------------
__global__ void k_down(int s) {   // direct, r = NL/s <= 16
    int r = NL / s;
    float inv = 1.0f / (float)r;
    int total = NB * s * ND;
    for (int t = blockIdx.x * blockDim.x + threadIdx.x; t < total;
         t += gridDim.x * blockDim.x) {
        int d = t & 511;
        int bt = t >> 9;
        int b = bt / s, tt = bt % s;
        const float* src = g_resid + (b * NL + tt * r) * ND + d;
        float acc = 0.f;
        for (int j = 0; j < r; j++) acc += src[j * ND];
        acc *= inv;
        split_h(acc, g_zH[t], g_zL[t]);
    }
}
__global__ void k_down1(int s, int segs) {
    float4* part = (float4*)g_part;
    int total = NB * s * segs * 128;
    for (int t = blockIdx.x * blockDim.x + threadIdx.x; t < total;
         t += gridDim.x * blockDim.x) {
        int d4 = t & 127;
        int rem = t >> 7;
        int seg = rem % segs;
        int bt = rem / segs;
        int b = bt / s, tt = bt % s;
        int r = NL / s;
        const float4* src = (const float4*)(g_resid + (b * NL + tt * r + seg * 16) * ND) + d4;
        float4 a = make_float4(0.f, 0.f, 0.f, 0.f);
        for (int j = 0; j < 16; j++) {
            float4 v = src[j * 128];
            a.x += v.x; a.y += v.y; a.z += v.z; a.w += v.w;
        }
        part[(bt * segs + seg) * 128 + d4] = a;
    }
}
__global__ void k_down2(int s, int segs) {
    const float4* part = (const float4*)g_part;
    float inv = (float)s * (1.0f / (float)NL);
    int total = NB * s * 128;
    for (int t = blockIdx.x * blockDim.x + threadIdx.x; t < total;
         t += gridDim.x * blockDim.x) {
        int d4 = t & 127;
        int bt = t >> 7;
        float4 a = make_float4(0.f, 0.f, 0.f, 0.f);
        for (int sg = 0; sg < segs; sg++) {
            float4 v = part[(bt * segs + sg) * 128 + d4];
            a.x += v.x; a.y += v.y; a.z += v.z; a.w += v.w;
        }
        int base = (bt << 9) + (d4 << 2);
        split_h(a.x * inv, g_zH[base + 0], g_zL[base + 0]);
        split_h(a.y * inv, g_zH[base + 1], g_zL[base + 1]);
        split_h(a.z * inv, g_zH[base + 2], g_zL[base + 2]);
        split_h(a.w * inv, g_zH[base + 3], g_zL[base + 3]);
    }
}

// ---------------- mma helpers ----------------
#define MMA16816(d, a, b0, b1) \
    asm volatile("mma.sync.aligned.m16n8k16.row.col.f32.f16.f16.f32 " \
        "{%0,%1,%2,%3}, {%4,%5,%6,%7}, {%8,%9}, {%0,%1,%2,%3};" \
        : "+f"((d)[0]), "+f"((d)[1]), "+f"((d)[2]), "+f"((d)[3]) \
        : "r"((a)[0]), "r"((a)[1]), "r"((a)[2]), "r"((a)[3]), "r"(b0), "r"(b1))
__device__ __forceinline__ uint32_t smem_u32(const void* p) {
    uint32_t a;
    asm("{ .reg .u64 t; cvta.to.shared.u64 t, %1; cvt.u32.u64 %0, t; }" : "=r"(a) : "l"(p));
    return a;
}
__device__ __forceinline__ void cp16(uint32_t s, const void* g, int sz) {
    asm volatile("cp.async.cg.shared.global [%0], [%1], 16, %2;"
        :: "r"(s), "l"(g), "r"(sz) : "memory");
}
#define CP_COMMIT() asm volatile("cp.async.commit_group;" ::: "memory")
#define CP_WAIT1()  asm volatile("cp.async.wait_group 1;" ::: "memory")
#define CP_WAIT0()  asm volatile("cp.async.wait_group 0;" ::: "memory")
__device__ __forceinline__ void ldsm4(uint32_t* r, uint32_t addr) {
    asm volatile("ldmatrix.sync.aligned.m8n8.x4.shared.b16 {%0,%1,%2,%3}, [%4];"
        : "=r"(r[0]), "=r"(r[1]), "=r"(r[2]), "=r"(r[3]) : "r"(addr));
}
#define PITCH_B 80

// ---------------- precompute: tapw = embed @ W_tap^T (3-term fp16) ------------
// grid (32, 4, 12); 80 KB dynamic smem, 2 stages of {Ah,Al,Bh,Bl}
#define STAGE3_B 40960
__global__ __launch_bounds__(256, 2) void k_gemm_pre() {
    extern __shared__ __align__(16) char dsm[];
    uint32_t sbase = smem_u32(dsm);
    int tid = threadIdx.x;
    int lane = tid & 31, wid = tid >> 5;
    int wm = wid >> 2, wn = wid & 3;
    int gr4 = lane >> 2, gc4 = lane & 3;
    int m0 = blockIdx.x * 128, n0 = blockIdx.y * 128;
    int z = blockIdx.z;   // p*3+tap

    const __half* AH = g_embH; const __half* ALo = g_embL;
    const __half* BH = g_wtH + (size_t)z * (ND * ND);
    const __half* BL = g_wtL + (size_t)z * (ND * ND);

    int lrow = tid >> 1;
    size_t aoff = (size_t)(m0 + lrow) * ND;
    size_t boff = (size_t)(n0 + lrow) * ND;
    int cByte = (tid & 1) * 32;
    const char* gAh = (const char*)(AH  + aoff) + cByte;
    const char* gAl = (const char*)(ALo + aoff) + cByte;
    const char* gBh = (const char*)(BH  + boff) + cByte;
    const char* gBl = (const char*)(BL  + boff) + cByte;
    uint32_t sOff = sbase + lrow * PITCH_B + cByte;

    int lm = lane & 15, lk = lane >> 4;
    uint32_t aFrag = sbase + (wm * 64 + lm) * PITCH_B + lk * 16;
    uint32_t bFrag = sbase + 20480 + (wn * 32 + lm) * PITCH_B + lk * 16;

    float acc[4][4][4];
#pragma unroll
    for (int i = 0; i < 4; i++)
#pragma unroll
        for (int j = 0; j < 4; j++)
#pragma unroll
            for (int q = 0; q < 4; q++) acc[i][j][q] = 0.f;

#define ISSUE3(stg, kb) do { \
        uint32_t so = sOff + (stg) * STAGE3_B; \
        int gb = (kb) * 64; \
        cp16(so,              gAh + gb,      16); \
        cp16(so + 16,         gAh + gb + 16, 16); \
        cp16(so + 10240,      gAl + gb,      16); \
        cp16(so + 10240 + 16, gAl + gb + 16, 16); \
        cp16(so + 20480,      gBh + gb,      16); \
        cp16(so + 20480 + 16, gBh + gb + 16, 16); \
        cp16(so + 30720,      gBl + gb,      16); \
        cp16(so + 30720 + 16, gBl + gb + 16, 16); \
        CP_COMMIT(); \
    } while (0)

    ISSUE3(0, 0);
    for (int kb = 0; kb < 16; kb++) {
        int st = kb & 1;
        __syncthreads();
        if (kb + 1 < 16) { ISSUE3((kb + 1) & 1, kb + 1); CP_WAIT1(); }
        else             { CP_WAIT0(); }
        __syncthreads();
        uint32_t sa = (uint32_t)st * STAGE3_B;
#pragma unroll
        for (int kp = 0; kp < 2; kp++) {
            uint32_t ah[4][4], al[4][4];
#pragma unroll
            for (int mt = 0; mt < 4; mt++) {
                uint32_t adr = aFrag + sa + mt * (16 * PITCH_B) + kp * 32;
                ldsm4(ah[mt], adr);
                ldsm4(al[mt], adr + 10240);
            }
#pragma unroll
            for (int ntp = 0; ntp < 2; ntp++) {
                uint32_t bh[4], bl[4];
                uint32_t badr = bFrag + sa + ntp * (16 * PITCH_B) + kp * 32;
                ldsm4(bh, badr);
                ldsm4(bl, badr + 10240);
#pragma unroll
                for (int mt = 0; mt < 4; mt++) {
                    MMA16816(acc[mt][2 * ntp],     ah[mt], bh[0], bh[2]);
                    MMA16816(acc[mt][2 * ntp],     al[mt], bh[0], bh[2]);
                    MMA16816(acc[mt][2 * ntp],     ah[mt], bl[0], bl[2]);
                    MMA16816(acc[mt][2 * ntp + 1], ah[mt], bh[1], bh[3]);
                    MMA16816(acc[mt][2 * ntp + 1], al[mt], bh[1], bh[3]);
                    MMA16816(acc[mt][2 * ntp + 1], ah[mt], bl[1], bl[3]);
                }
            }
        }
    }
#undef ISSUE3

    float* outz = g_tapw + (size_t)z * (NCB * ND);
#pragma unroll
    for (int mt = 0; mt < 4; mt++) {
#pragma unroll
        for (int h = 0; h < 2; h++) {
            int m = m0 + wm * 64 + mt * 16 + gr4 + 8 * h;
            float* crow = outz + ((size_t)m << 9);
#pragma unroll
            for (int nt = 0; nt < 4; nt++) {
                int c = n0 + wn * 32 + nt * 8 + 2 * gc4;
                *(float2*)(crow + c) =
                    make_float2(acc[mt][nt][2 * h], acc[mt][nt][2 * h + 1]);
            }
        }
    }
}

// ---------------- quantize: 1-term hi*hi GEMM + per-block top-2 candidates ----
#define STAGE1_B 20480
__global__ __launch_bounds__(256, 2) void k_quant1(int nTok) {
    extern __shared__ __align__(16) char dsm[];
    __shared__ unsigned long long smerge[128 * 8];
    uint32_t sbase = smem_u32(dsm);
    int tid = threadIdx.x;
    int lane = tid & 31, wid = tid >> 5;
    int wm = wid >> 2, wn = wid & 3;
    int gr4 = lane >> 2, gc4 = lane & 3;
    int m0 = blockIdx.x * 128, n0 = blockIdx.y * 128;

    int lrow = tid >> 1;
    int gm = m0 + lrow;
    int asz = (gm < nTok) ? 16 : 0;
    size_t aoff = (size_t)(gm < nTok ? gm : 0) * ND;
    size_t boff = (size_t)(n0 + lrow) * ND;
    int cByte = (tid & 1) * 32;
    const char* gAh = (const char*)(g_zH   + aoff) + cByte;
    const char* gBh = (const char*)(g_embH + boff) + cByte;
    uint32_t sOff = sbase + lrow * PITCH_B + cByte;

    int lm = lane & 15, lk = lane >> 4;
    uint32_t aFrag = sbase + (wm * 64 + lm) * PITCH_B + lk * 16;
    uint32_t bFrag = sbase + 10240 + (wn * 32 + lm) * PITCH_B + lk * 16;

    float acc[4][4][4];
#pragma unroll
    for (int i = 0; i < 4; i++)
#pragma unroll
        for (int j = 0; j < 4; j++)
#pragma unroll
            for (int q = 0; q < 4; q++) acc[i][j][q] = 0.f;

#define ISSUE1(stg, kb) do { \
        uint32_t so = sOff + (stg) * STAGE1_B; \
        int gb = (kb) * 64; \
        cp16(so,              gAh + gb,      asz); \
        cp16(so + 16,         gAh + gb + 16, asz); \
        cp16(so + 10240,      gBh + gb,      16); \
        cp16(so + 10240 + 16, gBh + gb + 16, 16); \
        CP_COMMIT(); \
    } while (0)

    ISSUE1(0, 0);
    for (int kb = 0; kb < 16; kb++) {
        int st = kb & 1;
        __syncthreads();
        if (kb + 1 < 16) { ISSUE1((kb + 1) & 1, kb + 1); CP_WAIT1(); }
        else             { CP_WAIT0(); }
        __syncthreads();
        uint32_t sa = (uint32_t)st * STAGE1_B;
#pragma unroll
        for (int kp = 0; kp < 2; kp++) {
            uint32_t ah[4][4];
#pragma unroll
            for (int mt = 0; mt < 4; mt++)
                ldsm4(ah[mt], aFrag + sa + mt * (16 * PITCH_B) + kp * 32);
#pragma unroll
            for (int ntp = 0; ntp < 2; ntp++) {
                uint32_t bh[4];
                ldsm4(bh, bFrag + sa + ntp * (16 * PITCH_B) + kp * 32);
#pragma unroll
                for (int mt = 0; mt < 4; mt++) {
                    MMA16816(acc[mt][2 * ntp],     ah[mt], bh[0], bh[2]);
                    MMA16816(acc[mt][2 * ntp + 1], ah[mt], bh[1], bh[3]);
                }
            }
        }
    }
#undef ISSUE1

    // per-row top-2 over this block's 128 codes
#pragma unroll
    for (int mt = 0; mt < 4; mt++) {
#pragma unroll
        for (int h = 0; h < 2; h++) {
            int row = wm * 64 + mt * 16 + gr4 + 8 * h;
            unsigned long long k1 = 0xFFFFFFFFFFFFFFFFULL, k2 = k1;
#pragma unroll
            for (int nt = 0; nt < 4; nt++) {
#pragma unroll
                for (int e = 0; e < 2; e++) {
                    int c = n0 + wn * 32 + nt * 8 + 2 * gc4 + e;
                    float sc = fmaf(-2.f, acc[mt][nt][2 * h + e], __ldg(&g_esq[c]));
                    unsigned u = __float_as_uint(sc);
                    u = (u & 0x80000000u) ? ~u : (u | 0x80000000u);
                    unsigned long long key = ((unsigned long long)u << 32) | (unsigned)c;
                    if (key < k1) { k2 = k1; k1 = key; }
                    else if (key < k2) { k2 = key; }
                }
            }
#pragma unroll
            for (int o = 1; o <= 2; o <<= 1) {
                unsigned long long o1 = __shfl_xor_sync(0xffffffffu, k1, o);
                unsigned long long o2 = __shfl_xor_sync(0xffffffffu, k2, o);
                unsigned long long lo = (k1 < o1) ? k1 : o1;
                unsigned long long hi = (k1 < o1) ? o1 : k1;
                unsigned long long mn2 = (k2 < o2) ? k2 : o2;
                k1 = lo;
                k2 = (hi < mn2) ? hi : mn2;
            }
            if (gc4 == 0) {
                smerge[row * 8 + wn * 2]     = k1;
                smerge[row * 8 + wn * 2 + 1] = k2;
            }
        }
    }
    __syncthreads();
    if (tid < 128 && (m0 + tid) < nTok) {
        unsigned long long k1 = 0xFFFFFFFFFFFFFFFFULL, k2 = k1;
#pragma unroll
        for (int j = 0; j < 8; j++) {
            unsigned long long k = smerge[tid * 8 + j];
            if (k < k1) { k2 = k1; k1 = k; }
            else if (k < k2) { k2 = k; }
        }
        unsigned* dst = g_cand + (size_t)(m0 + tid) * 64 + blockIdx.y * 2;
        dst[0] = (unsigned)(k1 & 0xffffffffu);
        dst[1] = (unsigned)(k2 & 0xffffffffu);
    }
}

// ---------------- exact fp32 rescore of 64 candidates/token ----------------
__global__ void k_rescore(const float* __restrict__ embed, int nTok) {
    int tok = blockIdx.x * 8 + (threadIdx.x >> 5);
    int lane = threadIdx.x & 31;
    if (tok >= nTok) return;
    float z[16];
#pragma unroll
    for (int j = 0; j < 16; j++) {
        int d = (size_t)0 + lane + 32 * j;
        int a = tok * ND + d;
        z[j] = __half2float(g_zH[a]) + __half2float(g_zL[a]);
    }
    float best = 3.4e38f; int bidx = 0x7fffffff;
    const unsigned* cand = g_cand + (size_t)tok * 64;
    for (int c = 0; c < 64; c++) {
        int idx = (int)cand[c];
        const float* e = embed + (size_t)idx * ND;
        float dot = 0.f;
#pragma unroll
        for (int j = 0; j < 16; j++)
            dot = fmaf(z[j], __ldg(e + lane + 32 * j), dot);
#pragma unroll
        for (int o = 16; o > 0; o >>= 1)
            dot += __shfl_xor_sync(0xffffffffu, dot, o);
        float sc = fmaf(-2.f, dot, g_esq[idx]);
        if (sc < best || (sc == best && idx < bidx)) { best = sc; bidx = idx; }
    }
    if (lane == 0) g_keys[tok] = (unsigned long long)(unsigned)bidx;
}

// ---------------- fused epilogue: gather tapw + interp + Phi mix + updates ----
__global__ void k_phi_ep(const float* __restrict__ embed,
                         const float* __restrict__ bias,
                         int s, int p, float* __restrict__ fhat) {
    int total = NB * NL * 128;
    float ratio = (float)s * (1.0f / 512.0f);
    for (int t = blockIdx.x * blockDim.x + threadIdx.x; t < total;
         t += gridDim.x * blockDim.x) {
        int d4 = t & 127;
        int bl = t >> 7;
        int b = bl >> 9, l = bl & 511;
        const unsigned long long* kb = g_keys + b * s;
        float4 sum = *(const float4*)(bias + (d4 << 2));
        float4 qup = make_float4(0.f, 0.f, 0.f, 0.f);
#pragma unroll
        for (int k = 0; k < 3; k++) {
            int lp = l + k - 1;
            if ((unsigned)lp < 512u) {
                float pos = ((float)lp + 0.5f) * ratio - 0.5f;
                float fl = floorf(pos);
                int i0 = (int)fl;
                float f = pos - fl;
                int ia, ib;
                if (i0 < 0)          { ia = 0;     ib = 0;     f = 0.f; }
                else if (i0 >= s - 1){ ia = s - 1; ib = s - 1; f = 0.f; }
                else                 { ia = i0;    ib = i0 + 1; }
                float w1 = 1.0f - f, w2 = f;
                int ca = (int)(unsigned)(kb[ia] & 0xffffffffULL);
                const float* base = g_tapw + (size_t)(p * 3 + k) * (NCB * ND);
                float4 va = *((const float4*)(base + ((size_t)ca << 9)) + d4);
                sum.x += w1 * va.x; sum.y += w1 * va.y;
                sum.z += w1 * va.z; sum.w += w1 * va.w;
                float4 ea;
                if (k == 1) {
                    ea = *((const float4*)(embed + ((size_t)ca << 9)) + d4);
                    qup.x = w1 * ea.x; qup.y = w1 * ea.y;
                    qup.z = w1 * ea.z; qup.w = w1 * ea.w;
                }
                if (w2 > 0.f) {
                    int cb = (int)(unsigned)(kb[ib] & 0xffffffffULL);
                    float4 vb = *((const float4*)(base + ((size_t)cb << 9)) + d4);
                    sum.x += w2 * vb.x; sum.y += w2 * vb.y;
                    sum.z += w2 * vb.z; sum.w += w2 * vb.w;
                    if (k == 1) {
                        float4 eb = *((const float4*)(embed + ((size_t)cb << 9)) + d4);
                        qup.x += w2 * eb.x; qup.y += w2 * eb.y;
                        qup.z += w2 * eb.z; qup.w += w2 * eb.w;
                    }
                }
            }
        }
        int adr = (bl << 9) + (d4 << 2);
        float4 fh = *(float4*)(fhat + adr);
        float4 rs = *(float4*)(g_resid + adr);
        float v0 = 0.5f * qup.x + 0.5f * sum.x;
        float v1 = 0.5f * qup.y + 0.5f * sum.y;
        float v2 = 0.5f * qup.z + 0.5f * sum.z;
        float v3 = 0.5f * qup.w + 0.5f * sum.w;
        fh.x += v0; fh.y += v1; fh.z += v2; fh.w += v3;
        rs.x -= v0; rs.y -= v1; rs.z -= v2; rs.w -= v3;
        *(float4*)(fhat + adr) = fh;
        *(float4*)(g_resid + adr) = rs;
    }
}

// ---------------- host ----------------
extern "C" void kernel_launch(void* const* d_in, const int* in_sizes, int n_in,
                              void* d_out, int out_size) {
    const float* x     = (const float*)d_in[0];
    const float* embed = (const float*)d_in[1];
    const float* phi_w = (const float*)d_in[2];
    const float* phi_b = (const float*)d_in[3];
    float* out = (float*)d_out;

    cudaFuncSetAttribute(k_gemm_pre,
                         cudaFuncAttributeMaxDynamicSharedMemorySize, 2 * STAGE3_B);
    cudaFuncSetAttribute(k_quant1,
                         cudaFuncAttributeMaxDynamicSharedMemorySize, 2 * STAGE1_B);

    // Replicate np.linspace(1/12, 11/12, 4) + first-min tie-break in double.
    double start = 1.0 / 3.0 / 4.0;
    double stop  = 1.0 - 1.0 / 3.0 / 4.0;
    double step  = (stop - start) / 3.0;
    double ticks[4] = { start, start + step, start + 2.0 * step, stop };
    int scales[10] = { 1, 2, 4, 8, 16, 32, 64, 128, 256, 512 };
    int phi_idx[10];
    for (int si = 0; si < 10; si++) {
        double v = (double)si / 9.0;
        int bk = 0; double bd = fabs(ticks[0] - v);
        for (int k = 1; k < 4; k++) {
            double dd = fabs(ticks[k] - v);
            if (dd < bd) { bd = dd; bk = k; }
        }
        phi_idx[si] = bk;
    }

    k_setup_esq<<<512, 256>>>(embed);
    k_split_emb<<<1024, 256>>>(embed);
    k_setup_wt<<<1024, 256>>>(phi_w);
    k_init<<<2048, 256>>>(x, out);
    // precompute all 12 (phi,tap) codebook transforms upfront (loop-independent)
    k_gemm_pre<<<dim3(32, 4, 12), 256, 2 * STAGE3_B>>>();

    for (int si = 0; si < 10; si++) {
        int s = scales[si];
        int nTok = NB * s;

        if (s <= 16) {
            int segs = (NL / s) / 16;
            int t1 = NB * s * segs * 128;
            int b1 = (t1 + 255) / 256; if (b1 > 2048) b1 = 2048;
            k_down1<<<b1, 256>>>(s, segs);
            int t2 = NB * s * 128;
            int b2 = (t2 + 255) / 256;
            k_down2<<<b2, 256>>>(s, segs);
        } else {
            int total = NB * s * ND;
            int blk = (total + 255) / 256; if (blk > 8192) blk = 8192;
            k_down<<<blk, 256>>>(s);
        }

        int mTiles = (nTok + 127) / 128;
        k_quant1<<<dim3(mTiles, NCB / 128), 256, 2 * STAGE1_B>>>(nTok);
        k_rescore<<<(nTok + 7) / 8, 256>>>(embed, nTok);
        k_phi_ep<<<4096, 256>>>(embed, phi_b + phi_idx[si] * ND, s, phi_idx[si], out);
    }
}

// round 11
// speedup vs baseline: 4.8331x; 1.0018x over previous
#include <cuda_runtime.h>
#include <cuda_fp16.h>
#include <math.h>
#include <stdint.h>

#define NB 16
#define NL 512
#define ND 512
#define NCB 4096
#define NTOT (NB*NL*ND)

// ---------------- scratch (device globals, allocation-free) ----------------
__device__ float g_resid[NTOT];
__device__ float g_tapw[12 * NCB * ND];          // [(p*3+tap)][code][o]
__device__ unsigned long long g_keys[NB*NL];
__device__ unsigned g_cand[NB*NL*64];
__device__ float g_esq[NCB];
__device__ float g_part[NB*32*ND];
__device__ __half g_embH[NCB*ND], g_embL[NCB*ND];
__device__ __half g_zH[NB*NL*ND], g_zL[NB*NL*ND];
__device__ __half g_wtH[4*3*ND*ND], g_wtL[4*3*ND*ND];  // [p][tap][o][i]

__device__ __forceinline__ void split_h(float x, __half& h, __half& l) {
    h = __float2half_rn(x);
    l = __float2half_rn(x - __half2float(h));
}

// ---------------- setup ----------------
__global__ void k_setup_esq(const float* __restrict__ embed) {
    int gw = (blockIdx.x * blockDim.x + threadIdx.x) >> 5;
    int lane = threadIdx.x & 31;
    if (gw >= NCB) return;
    const float* e = embed + gw * ND;
    float s = 0.f;
    for (int d = lane; d < ND; d += 32) { float v = e[d]; s = fmaf(v, v, s); }
    for (int o = 16; o > 0; o >>= 1) s += __shfl_xor_sync(0xffffffffu, s, o);
    if (lane == 0) g_esq[gw] = s;
}
__global__ void k_split_emb(const float* __restrict__ embed) {
    for (int t = blockIdx.x * blockDim.x + threadIdx.x; t < NCB * ND;
         t += gridDim.x * blockDim.x)
        split_h(embed[t], g_embH[t], g_embL[t]);
}
__global__ void k_setup_wt(const float* __restrict__ phi_w) {
    int total = 4 * 3 * ND * ND;
    for (int t = blockIdx.x * blockDim.x + threadIdx.x; t < total;
         t += gridDim.x * blockDim.x) {
        int i = t & 511;
        int q = t >> 9;
        int o = q & 511; q >>= 9;
        int tap = q % 3;
        int p = q / 3;
        split_h(phi_w[((p * ND + o) * ND + i) * 3 + tap], g_wtH[t], g_wtL[t]);
    }
}

// ---------------- downsample (block mean) + split ----------------
__global__ void k_down(int s, const float* __restrict__ src0) {   // r <= 16
    int r = NL / s;
    float inv = 1.0f / (float)r;
    int total = NB * s * ND;
    for (int t = blockIdx.x * blockDim.x + threadIdx.x; t < total;
         t += gridDim.x * blockDim.x) {
        int d = t & 511;
        int bt = t >> 9;
        int b = bt / s, tt = bt % s;
        const float* src = src0 + (b * NL + tt * r) * ND + d;
        float acc = 0.f;
        for (int j = 0; j < r; j++) acc += src[j * ND];
        acc *= inv;
        split_h(acc, g_zH[t], g_zL[t]);
    }
}
__global__ void k_down1(int s, int segs, const float* __restrict__ src0) {
    float4* part = (float4*)g_part;
    int total = NB * s * segs * 128;
    for (int t = blockIdx.x * blockDim.x + threadIdx.x; t < total;
         t += gridDim.x * blockDim.x) {
        int d4 = t & 127;
        int rem = t >> 7;
        int seg = rem % segs;
        int bt = rem / segs;
        int b = bt / s, tt = bt % s;
        int r = NL / s;
        const float4* src = (const float4*)(src0 + (b * NL + tt * r + seg * 16) * ND) + d4;
        float4 a = make_float4(0.f, 0.f, 0.f, 0.f);
        for (int j = 0; j < 16; j++) {
            float4 v = src[j * 128];
            a.x += v.x; a.y += v.y; a.z += v.z; a.w += v.w;
        }
        part[(bt * segs + seg) * 128 + d4] = a;
    }
}
__global__ void k_down2(int s, int segs) {
    const float4* part = (const float4*)g_part;
    float inv = (float)s * (1.0f / (float)NL);
    int total = NB * s * 128;
    for (int t = blockIdx.x * blockDim.x + threadIdx.x; t < total;
         t += gridDim.x * blockDim.x) {
        int d4 = t & 127;
        int bt = t >> 7;
        float4 a = make_float4(0.f, 0.f, 0.f, 0.f);
        for (int sg = 0; sg < segs; sg++) {
            float4 v = part[(bt * segs + sg) * 128 + d4];
            a.x += v.x; a.y += v.y; a.z += v.z; a.w += v.w;
        }
        int base = (bt << 9) + (d4 << 2);
        split_h(a.x * inv, g_zH[base + 0], g_zL[base + 0]);
        split_h(a.y * inv, g_zH[base + 1], g_zL[base + 1]);
        split_h(a.z * inv, g_zH[base + 2], g_zL[base + 2]);
        split_h(a.w * inv, g_zH[base + 3], g_zL[base + 3]);
    }
}

// ---------------- mma helpers ----------------
#define MMA16816(d, a, b0, b1) \
    asm volatile("mma.sync.aligned.m16n8k16.row.col.f32.f16.f16.f32 " \
        "{%0,%1,%2,%3}, {%4,%5,%6,%7}, {%8,%9}, {%0,%1,%2,%3};" \
        : "+f"((d)[0]), "+f"((d)[1]), "+f"((d)[2]), "+f"((d)[3]) \
        : "r"((a)[0]), "r"((a)[1]), "r"((a)[2]), "r"((a)[3]), "r"(b0), "r"(b1))
__device__ __forceinline__ uint32_t smem_u32(const void* p) {
    uint32_t a;
    asm("{ .reg .u64 t; cvta.to.shared.u64 t, %1; cvt.u32.u64 %0, t; }" : "=r"(a) : "l"(p));
    return a;
}
__device__ __forceinline__ void cp16(uint32_t s, const void* g, int sz) {
    asm volatile("cp.async.cg.shared.global [%0], [%1], 16, %2;"
        :: "r"(s), "l"(g), "r"(sz) : "memory");
}
#define CP_COMMIT() asm volatile("cp.async.commit_group;" ::: "memory")
#define CP_WAIT1()  asm volatile("cp.async.wait_group 1;" ::: "memory")
#define CP_WAIT0()  asm volatile("cp.async.wait_group 0;" ::: "memory")
__device__ __forceinline__ void ldsm4(uint32_t* r, uint32_t addr) {
    asm volatile("ldmatrix.sync.aligned.m8n8.x4.shared.b16 {%0,%1,%2,%3}, [%4];"
        : "=r"(r[0]), "=r"(r[1]), "=r"(r[2]), "=r"(r[3]) : "r"(addr));
}
#define PITCH_B 80

// ---------------- precompute: tapw = embed @ W_tap^T (3-term fp16) ------------
// stage: Ah[0,10240) Al[10240,20480) Bh[20480,30720) Bl[30720,40960)
#define STAGE3_B 40960
__global__ __launch_bounds__(256, 2) void k_gemm_pre() {
    extern __shared__ __align__(16) char dsm[];
    uint32_t sbase = smem_u32(dsm);
    int tid = threadIdx.x;
    int lane = tid & 31, wid = tid >> 5;
    int wm = wid >> 2, wn = wid & 3;
    int gr4 = lane >> 2, gc4 = lane & 3;
    int m0 = blockIdx.x * 128, n0 = blockIdx.y * 128;
    int z = blockIdx.z;   // p*3+tap

    const __half* BH = g_wtH + (size_t)z * (ND * ND);
    const __half* BL = g_wtL + (size_t)z * (ND * ND);

    int lrow = tid >> 1;
    size_t aoff = (size_t)(m0 + lrow) * ND;
    size_t boff = (size_t)(n0 + lrow) * ND;
    int cByte = (tid & 1) * 32;
    const char* gAh = (const char*)(g_embH + aoff) + cByte;
    const char* gAl = (const char*)(g_embL + aoff) + cByte;
    const char* gBh = (const char*)(BH     + boff) + cByte;
    const char* gBl = (const char*)(BL     + boff) + cByte;
    uint32_t sOff = sbase + lrow * PITCH_B + cByte;

    int lm = lane & 15, lk = lane >> 4;
    uint32_t aFrag = sbase + (wm * 64 + lm) * PITCH_B + lk * 16;
    uint32_t bFrag = sbase + 20480 + (wn * 32 + lm) * PITCH_B + lk * 16;

    float acc[4][4][4];
#pragma unroll
    for (int i = 0; i < 4; i++)
#pragma unroll
        for (int j = 0; j < 4; j++)
#pragma unroll
            for (int q = 0; q < 4; q++) acc[i][j][q] = 0.f;

#define ISSUE3(stg, kb) do { \
        uint32_t so = sOff + (stg) * STAGE3_B; \
        int gb = (kb) * 64; \
        cp16(so,              gAh + gb,      16); \
        cp16(so + 16,         gAh + gb + 16, 16); \
        cp16(so + 10240,      gAl + gb,      16); \
        cp16(so + 10240 + 16, gAl + gb + 16, 16); \
        cp16(so + 20480,      gBh + gb,      16); \
        cp16(so + 20480 + 16, gBh + gb + 16, 16); \
        cp16(so + 30720,      gBl + gb,      16); \
        cp16(so + 30720 + 16, gBl + gb + 16, 16); \
        CP_COMMIT(); \
    } while (0)

    ISSUE3(0, 0);
    for (int kb = 0; kb < 16; kb++) {
        int st = kb & 1;
        __syncthreads();
        if (kb + 1 < 16) { ISSUE3((kb + 1) & 1, kb + 1); CP_WAIT1(); }
        else             { CP_WAIT0(); }
        __syncthreads();
        uint32_t sa = (uint32_t)st * STAGE3_B;
#pragma unroll
        for (int kp = 0; kp < 2; kp++) {
            uint32_t ah[4][4], al[4][4];
#pragma unroll
            for (int mt = 0; mt < 4; mt++) {
                uint32_t adr = aFrag + sa + mt * (16 * PITCH_B) + kp * 32;
                ldsm4(ah[mt], adr);
                ldsm4(al[mt], adr + 10240);
            }
#pragma unroll
            for (int ntp = 0; ntp < 2; ntp++) {
                uint32_t bh[4], bl[4];
                uint32_t badr = bFrag + sa + ntp * (16 * PITCH_B) + kp * 32;
                ldsm4(bh, badr);
                ldsm4(bl, badr + 10240);
#pragma unroll
                for (int mt = 0; mt < 4; mt++) {
                    MMA16816(acc[mt][2 * ntp],     ah[mt], bh[0], bh[2]);
                    MMA16816(acc[mt][2 * ntp],     al[mt], bh[0], bh[2]);
                    MMA16816(acc[mt][2 * ntp],     ah[mt], bl[0], bl[2]);
                    MMA16816(acc[mt][2 * ntp + 1], ah[mt], bh[1], bh[3]);
                    MMA16816(acc[mt][2 * ntp + 1], al[mt], bh[1], bh[3]);
                    MMA16816(acc[mt][2 * ntp + 1], ah[mt], bl[1], bl[3]);
                }
            }
        }
    }
#undef ISSUE3

    float* outz = g_tapw + (size_t)z * (NCB * ND);
#pragma unroll
    for (int mt = 0; mt < 4; mt++) {
#pragma unroll
        for (int h = 0; h < 2; h++) {
            int m = m0 + wm * 64 + mt * 16 + gr4 + 8 * h;
            float* crow = outz + ((size_t)m << 9);
#pragma unroll
            for (int nt = 0; nt < 4; nt++) {
                int c = n0 + wn * 32 + nt * 8 + 2 * gc4;
                *(float2*)(crow + c) =
                    make_float2(acc[mt][nt][2 * h], acc[mt][nt][2 * h + 1]);
            }
        }
    }
}

// ---------------- quantize: 1-term hi*hi GEMM + per-block top-2 candidates ----
#define STAGE1_B 20480
__global__ __launch_bounds__(256, 2) void k_quant1(int nTok) {
    extern __shared__ __align__(16) char dsm[];
    __shared__ unsigned long long smerge[128 * 8];
    uint32_t sbase = smem_u32(dsm);
    int tid = threadIdx.x;
    int lane = tid & 31, wid = tid >> 5;
    int wm = wid >> 2, wn = wid & 3;
    int gr4 = lane >> 2, gc4 = lane & 3;
    int m0 = blockIdx.x * 128, n0 = blockIdx.y * 128;

    int lrow = tid >> 1;
    int gm = m0 + lrow;
    int asz = (gm < nTok) ? 16 : 0;
    size_t aoff = (size_t)(gm < nTok ? gm : 0) * ND;
    size_t boff = (size_t)(n0 + lrow) * ND;
    int cByte = (tid & 1) * 32;
    const char* gAh = (const char*)(g_zH   + aoff) + cByte;
    const char* gBh = (const char*)(g_embH + boff) + cByte;
    uint32_t sOff = sbase + lrow * PITCH_B + cByte;

    int lm = lane & 15, lk = lane >> 4;
    uint32_t aFrag = sbase + (wm * 64 + lm) * PITCH_B + lk * 16;
    uint32_t bFrag = sbase + 10240 + (wn * 32 + lm) * PITCH_B + lk * 16;

    float acc[4][4][4];
#pragma unroll
    for (int i = 0; i < 4; i++)
#pragma unroll
        for (int j = 0; j < 4; j++)
#pragma unroll
            for (int q = 0; q < 4; q++) acc[i][j][q] = 0.f;

#define ISSUE1(stg, kb) do { \
        uint32_t so = sOff + (stg) * STAGE1_B; \
        int gb = (kb) * 64; \
        cp16(so,              gAh + gb,      asz); \
        cp16(so + 16,         gAh + gb + 16, asz); \
        cp16(so + 10240,      gBh + gb,      16); \
        cp16(so + 10240 + 16, gBh + gb + 16, 16); \
        CP_COMMIT(); \
    } while (0)

    ISSUE1(0, 0);
    for (int kb = 0; kb < 16; kb++) {
        int st = kb & 1;
        __syncthreads();
        if (kb + 1 < 16) { ISSUE1((kb + 1) & 1, kb + 1); CP_WAIT1(); }
        else             { CP_WAIT0(); }
        __syncthreads();
        uint32_t sa = (uint32_t)st * STAGE1_B;
#pragma unroll
        for (int kp = 0; kp < 2; kp++) {
            uint32_t ah[4][4];
#pragma unroll
            for (int mt = 0; mt < 4; mt++)
                ldsm4(ah[mt], aFrag + sa + mt * (16 * PITCH_B) + kp * 32);
#pragma unroll
            for (int ntp = 0; ntp < 2; ntp++) {
                uint32_t bh[4];
                ldsm4(bh, bFrag + sa + ntp * (16 * PITCH_B) + kp * 32);
#pragma unroll
                for (int mt = 0; mt < 4; mt++) {
                    MMA16816(acc[mt][2 * ntp],     ah[mt], bh[0], bh[2]);
                    MMA16816(acc[mt][2 * ntp + 1], ah[mt], bh[1], bh[3]);
                }
            }
        }
    }
#undef ISSUE1

#pragma unroll
    for (int mt = 0; mt < 4; mt++) {
#pragma unroll
        for (int h = 0; h < 2; h++) {
            int row = wm * 64 + mt * 16 + gr4 + 8 * h;
            unsigned long long k1 = 0xFFFFFFFFFFFFFFFFULL, k2 = k1;
#pragma unroll
            for (int nt = 0; nt < 4; nt++) {
#pragma unroll
                for (int e = 0; e < 2; e++) {
                    int c = n0 + wn * 32 + nt * 8 + 2 * gc4 + e;
                    float sc = fmaf(-2.f, acc[mt][nt][2 * h + e], __ldg(&g_esq[c]));
                    unsigned u = __float_as_uint(sc);
                    u = (u & 0x80000000u) ? ~u : (u | 0x80000000u);
                    unsigned long long key = ((unsigned long long)u << 32) | (unsigned)c;
                    if (key < k1) { k2 = k1; k1 = key; }
                    else if (key < k2) { k2 = key; }
                }
            }
#pragma unroll
            for (int o = 1; o <= 2; o <<= 1) {
                unsigned long long o1 = __shfl_xor_sync(0xffffffffu, k1, o);
                unsigned long long o2 = __shfl_xor_sync(0xffffffffu, k2, o);
                unsigned long long lo = (k1 < o1) ? k1 : o1;
                unsigned long long hi = (k1 < o1) ? o1 : k1;
                unsigned long long mn2 = (k2 < o2) ? k2 : o2;
                k1 = lo;
                k2 = (hi < mn2) ? hi : mn2;
            }
            if (gc4 == 0) {
                smerge[row * 8 + wn * 2]     = k1;
                smerge[row * 8 + wn * 2 + 1] = k2;
            }
        }
    }
    __syncthreads();
    if (tid < 128 && (m0 + tid) < nTok) {
        unsigned long long k1 = 0xFFFFFFFFFFFFFFFFULL, k2 = k1;
#pragma unroll
        for (int j = 0; j < 8; j++) {
            unsigned long long k = smerge[tid * 8 + j];
            if (k < k1) { k2 = k1; k1 = k; }
            else if (k < k2) { k2 = k; }
        }
        unsigned* dst = g_cand + (size_t)(m0 + tid) * 64 + blockIdx.y * 2;
        dst[0] = (unsigned)(k1 & 0xffffffffu);
        dst[1] = (unsigned)(k2 & 0xffffffffu);
    }
}

// ---------------- exact fp32 rescore of 64 candidates/token ----------------
__global__ void k_rescore(const float* __restrict__ embed, int nTok) {
    int tok = blockIdx.x * 8 + (threadIdx.x >> 5);
    int lane = threadIdx.x & 31;
    if (tok >= nTok) return;
    float z[16];
#pragma unroll
    for (int j = 0; j < 16; j++) {
        int a = tok * ND + lane + 32 * j;
        z[j] = __half2float(g_zH[a]) + __half2float(g_zL[a]);
    }
    float best = 3.4e38f; int bidx = 0x7fffffff;
    const unsigned* cand = g_cand + (size_t)tok * 64;
    for (int c = 0; c < 64; c++) {
        int idx = (int)cand[c];
        const float* e = embed + (size_t)idx * ND;
        float dot = 0.f;
#pragma unroll
        for (int j = 0; j < 16; j++)
            dot = fmaf(z[j], __ldg(e + lane + 32 * j), dot);
#pragma unroll
        for (int o = 16; o > 0; o >>= 1)
            dot += __shfl_xor_sync(0xffffffffu, dot, o);
        float sc = fmaf(-2.f, dot, g_esq[idx]);
        if (sc < best || (sc == best && idx < bidx)) { best = sc; bidx = idx; }
    }
    if (lane == 0) g_keys[tok] = (unsigned long long)(unsigned)bidx;
}

// ---------------- fused epilogue: gather tapw + interp + Phi mix + resid ------
__global__ void k_phi_ep(const float* __restrict__ embed,
                         const float* __restrict__ bias,
                         int s, int p, const float* __restrict__ rsrc) {
    int total = NB * NL * 128;
    float ratio = (float)s * (1.0f / 512.0f);
    for (int t = blockIdx.x * blockDim.x + threadIdx.x; t < total;
         t += gridDim.x * blockDim.x) {
        int d4 = t & 127;
        int bl = t >> 7;
        int b = bl >> 9, l = bl & 511;
        const unsigned long long* kb = g_keys + b * s;
        float4 sum = *(const float4*)(bias + (d4 << 2));
        float4 qup = make_float4(0.f, 0.f, 0.f, 0.f);
#pragma unroll
        for (int k = 0; k < 3; k++) {
            int lp = l + k - 1;
            if ((unsigned)lp < 512u) {
                float pos = ((float)lp + 0.5f) * ratio - 0.5f;
                float fl = floorf(pos);
                int i0 = (int)fl;
                float f = pos - fl;
                int ia, ib;
                if (i0 < 0)          { ia = 0;     ib = 0;     f = 0.f; }
                else if (i0 >= s - 1){ ia = s - 1; ib = s - 1; f = 0.f; }
                else                 { ia = i0;    ib = i0 + 1; }
                float w1 = 1.0f - f, w2 = f;
                int ca = (int)(unsigned)(kb[ia] & 0xffffffffULL);
                const float* base = g_tapw + (size_t)(p * 3 + k) * (NCB * ND);
                float4 va = *((const float4*)(base + ((size_t)ca << 9)) + d4);
                sum.x += w1 * va.x; sum.y += w1 * va.y;
                sum.z += w1 * va.z; sum.w += w1 * va.w;
                if (k == 1) {
                    float4 ea = *((const float4*)(embed + ((size_t)ca << 9)) + d4);
                    qup.x = w1 * ea.x; qup.y = w1 * ea.y;
                    qup.z = w1 * ea.z; qup.w = w1 * ea.w;
                }
                if (w2 > 0.f) {
                    int cb = (int)(unsigned)(kb[ib] & 0xffffffffULL);
                    float4 vb = *((const float4*)(base + ((size_t)cb << 9)) + d4);
                    sum.x += w2 * vb.x; sum.y += w2 * vb.y;
                    sum.z += w2 * vb.z; sum.w += w2 * vb.w;
                    if (k == 1) {
                        float4 eb = *((const float4*)(embed + ((size_t)cb << 9)) + d4);
                        qup.x += w2 * eb.x; qup.y += w2 * eb.y;
                        qup.z += w2 * eb.z; qup.w += w2 * eb.w;
                    }
                }
            }
        }
        int adr = (bl << 9) + (d4 << 2);
        float4 rs = *(const float4*)(rsrc + adr);
        rs.x -= 0.5f * qup.x + 0.5f * sum.x;
        rs.y -= 0.5f * qup.y + 0.5f * sum.y;
        rs.z -= 0.5f * qup.z + 0.5f * sum.z;
        rs.w -= 0.5f * qup.w + 0.5f * sum.w;
        *(float4*)(g_resid + adr) = rs;
    }
}

// ---------------- final: out = x - resid ----------------
__global__ void k_final(const float* __restrict__ x, float* __restrict__ out) {
    for (int t = blockIdx.x * blockDim.x + threadIdx.x; t < NTOT;
         t += gridDim.x * blockDim.x)
        out[t] = x[t] - g_resid[t];
}

// ---------------- host ----------------
extern "C" void kernel_launch(void* const* d_in, const int* in_sizes, int n_in,
                              void* d_out, int out_size) {
    const float* x     = (const float*)d_in[0];
    const float* embed = (const float*)d_in[1];
    const float* phi_w = (const float*)d_in[2];
    const float* phi_b = (const float*)d_in[3];
    float* out = (float*)d_out;

    float* residPtr = nullptr;
    cudaGetSymbolAddress((void**)&residPtr, g_resid);

    cudaFuncSetAttribute(k_gemm_pre,
                         cudaFuncAttributeMaxDynamicSharedMemorySize, 2 * STAGE3_B);
    cudaFuncSetAttribute(k_quant1,
                         cudaFuncAttributeMaxDynamicSharedMemorySize, 2 * STAGE1_B);

    // Replicate np.linspace(1/12, 11/12, 4) + first-min tie-break in double.
    double start = 1.0 / 3.0 / 4.0;
    double stop  = 1.0 - 1.0 / 3.0 / 4.0;
    double step  = (stop - start) / 3.0;
    double ticks[4] = { start, start + step, start + 2.0 * step, stop };
    int scales[10] = { 1, 2, 4, 8, 16, 32, 64, 128, 256, 512 };
    int phi_idx[10];
    for (int si = 0; si < 10; si++) {
        double v = (double)si / 9.0;
        int bk = 0; double bd = fabs(ticks[0] - v);
        for (int k = 1; k < 4; k++) {
            double dd = fabs(ticks[k] - v);
            if (dd < bd) { bd = dd; bk = k; }
        }
        phi_idx[si] = bk;
    }

    k_setup_esq<<<512, 256>>>(embed);
    k_split_emb<<<1024, 256>>>(embed);
    k_setup_wt<<<1024, 256>>>(phi_w);
    k_gemm_pre<<<dim3(32, 4, 12), 256, 2 * STAGE3_B>>>();

    for (int si = 0; si < 10; si++) {
        int s = scales[si];
        int nTok = NB * s;
        const float* src = (si == 0) ? x : residPtr;

        if (s <= 16) {
            int segs = (NL / s) / 16;
            int t1 = NB * s * segs * 128;
            int b1 = (t1 + 255) / 256; if (b1 > 2048) b1 = 2048;
            k_down1<<<b1, 256>>>(s, segs, src);
            int t2 = NB * s * 128;
            int b2 = (t2 + 255) / 256;
            k_down2<<<b2, 256>>>(s, segs);
        } else {
            int total = NB * s * ND;
            int blk = (total + 255) / 256; if (blk > 8192) blk = 8192;
            k_down<<<blk, 256>>>(s, src);
        }

        int mTiles = (nTok + 127) / 128;
        k_quant1<<<dim3(mTiles, NCB / 128), 256, 2 * STAGE1_B>>>(nTok);
        k_rescore<<<(nTok + 7) / 8, 256>>>(embed, nTok);
        k_phi_ep<<<4096, 256>>>(embed, phi_b + phi_idx[si] * ND, s, phi_idx[si], src);
    }
    k_final<<<2048, 256>>>(x, out);
}

// round 12
// speedup vs baseline: 5.4530x; 1.1283x over previous
#include <cuda_runtime.h>
#include <cuda_fp16.h>
#include <math.h>
#include <stdint.h>

#define NB 16
#define NL 512
#define ND 512
#define NCB 4096
#define NTOT (NB*NL*ND)

// ---------------- scratch (device globals, allocation-free) ----------------
__device__ float g_resid[NTOT];
__device__ float g_tapw[12 * NCB * ND];          // [(p*3+tap)][code][o]
__device__ unsigned long long g_keys[NB*NL];
__device__ unsigned g_cand[NB*NL*64];
__device__ float g_esq[NCB];
__device__ float g_part[NB*32*ND];
__device__ __half g_embH[NCB*ND], g_embL[NCB*ND];
__device__ __half g_zH[NB*NL*ND], g_zL[NB*NL*ND];
__device__ __half g_wtH[4*3*ND*ND], g_wtL[4*3*ND*ND];  // [p][tap][o][i]

__device__ __forceinline__ void split_h(float x, __half& h, __half& l) {
    h = __float2half_rn(x);
    l = __float2half_rn(x - __half2float(h));
}

// ---------------- setup ----------------
__global__ void k_setup_esq(const float* __restrict__ embed) {
    int gw = (blockIdx.x * blockDim.x + threadIdx.x) >> 5;
    int lane = threadIdx.x & 31;
    if (gw >= NCB) return;
    const float* e = embed + gw * ND;
    float s = 0.f;
    for (int d = lane; d < ND; d += 32) { float v = e[d]; s = fmaf(v, v, s); }
    for (int o = 16; o > 0; o >>= 1) s += __shfl_xor_sync(0xffffffffu, s, o);
    if (lane == 0) g_esq[gw] = s;
}
__global__ void k_split_emb(const float* __restrict__ embed) {
    for (int t = blockIdx.x * blockDim.x + threadIdx.x; t < NCB * ND;
         t += gridDim.x * blockDim.x)
        split_h(embed[t], g_embH[t], g_embL[t]);
}
__global__ void k_setup_wt(const float* __restrict__ phi_w) {
    int total = 4 * 3 * ND * ND;
    for (int t = blockIdx.x * blockDim.x + threadIdx.x; t < total;
         t += gridDim.x * blockDim.x) {
        int i = t & 511;
        int q = t >> 9;
        int o = q & 511; q >>= 9;
        int tap = q % 3;
        int p = q / 3;
        split_h(phi_w[((p * ND + o) * ND + i) * 3 + tap], g_wtH[t], g_wtL[t]);
    }
}

// ---------------- downsample (block mean) + split ----------------
__global__ void k_down(int s, const float* __restrict__ src0) {   // r <= 16
    int r = NL / s;
    float inv = 1.0f / (float)r;
    int total = NB * s * ND;
    for (int t = blockIdx.x * blockDim.x + threadIdx.x; t < total;
         t += gridDim.x * blockDim.x) {
        int d = t & 511;
        int bt = t >> 9;
        int b = bt / s, tt = bt % s;
        const float* src = src0 + (b * NL + tt * r) * ND + d;
        float acc = 0.f;
        for (int j = 0; j < r; j++) acc += src[j * ND];
        acc *= inv;
        split_h(acc, g_zH[t], g_zL[t]);
    }
}
__global__ void k_down1(int s, int segs, const float* __restrict__ src0) {
    float4* part = (float4*)g_part;
    int total = NB * s * segs * 128;
    for (int t = blockIdx.x * blockDim.x + threadIdx.x; t < total;
         t += gridDim.x * blockDim.x) {
        int d4 = t & 127;
        int rem = t >> 7;
        int seg = rem % segs;
        int bt = rem / segs;
        int b = bt / s, tt = bt % s;
        int r = NL / s;
        const float4* src = (const float4*)(src0 + (b * NL + tt * r + seg * 16) * ND) + d4;
        float4 a = make_float4(0.f, 0.f, 0.f, 0.f);
        for (int j = 0; j < 16; j++) {
            float4 v = src[j * 128];
            a.x += v.x; a.y += v.y; a.z += v.z; a.w += v.w;
        }
        part[(bt * segs + seg) * 128 + d4] = a;
    }
}
__global__ void k_down2(int s, int segs) {
    const float4* part = (const float4*)g_part;
    float inv = (float)s * (1.0f / (float)NL);
    int total = NB * s * 128;
    for (int t = blockIdx.x * blockDim.x + threadIdx.x; t < total;
         t += gridDim.x * blockDim.x) {
        int d4 = t & 127;
        int bt = t >> 7;
        float4 a = make_float4(0.f, 0.f, 0.f, 0.f);
        for (int sg = 0; sg < segs; sg++) {
            float4 v = part[(bt * segs + sg) * 128 + d4];
            a.x += v.x; a.y += v.y; a.z += v.z; a.w += v.w;
        }
        int base = (bt << 9) + (d4 << 2);
        split_h(a.x * inv, g_zH[base + 0], g_zL[base + 0]);
        split_h(a.y * inv, g_zH[base + 1], g_zL[base + 1]);
        split_h(a.z * inv, g_zH[base + 2], g_zL[base + 2]);
        split_h(a.w * inv, g_zH[base + 3], g_zL[base + 3]);
    }
}

// ---------------- mma helpers ----------------
#define MMA16816(d, a, b0, b1) \
    asm volatile("mma.sync.aligned.m16n8k16.row.col.f32.f16.f16.f32 " \
        "{%0,%1,%2,%3}, {%4,%5,%6,%7}, {%8,%9}, {%0,%1,%2,%3};" \
        : "+f"((d)[0]), "+f"((d)[1]), "+f"((d)[2]), "+f"((d)[3]) \
        : "r"((a)[0]), "r"((a)[1]), "r"((a)[2]), "r"((a)[3]), "r"(b0), "r"(b1))
__device__ __forceinline__ uint32_t smem_u32(const void* p) {
    uint32_t a;
    asm("{ .reg .u64 t; cvta.to.shared.u64 t, %1; cvt.u32.u64 %0, t; }" : "=r"(a) : "l"(p));
    return a;
}
__device__ __forceinline__ void cp16(uint32_t s, const void* g, int sz) {
    asm volatile("cp.async.cg.shared.global [%0], [%1], 16, %2;"
        :: "r"(s), "l"(g), "r"(sz) : "memory");
}
#define CP_COMMIT() asm volatile("cp.async.commit_group;" ::: "memory")
#define CP_WAIT1()  asm volatile("cp.async.wait_group 1;" ::: "memory")
#define CP_WAIT0()  asm volatile("cp.async.wait_group 0;" ::: "memory")
__device__ __forceinline__ void ldsm4(uint32_t* r, uint32_t addr) {
    asm volatile("ldmatrix.sync.aligned.m8n8.x4.shared.b16 {%0,%1,%2,%3}, [%4];"
        : "=r"(r[0]), "=r"(r[1]), "=r"(r[2]), "=r"(r[3]) : "r"(addr));
}
#define PITCH_B 80

// ---------------- precompute: tapw = embed @ W_tap^T (3-term fp16), per-phi ---
// stage: Ah[0,10240) Al[10240,20480) Bh[20480,30720) Bl[30720,40960)
#define STAGE3_B 40960
__global__ __launch_bounds__(256, 2) void k_gemm_pre(int p) {
    extern __shared__ __align__(16) char dsm[];
    uint32_t sbase = smem_u32(dsm);
    int tid = threadIdx.x;
    int lane = tid & 31, wid = tid >> 5;
    int wm = wid >> 2, wn = wid & 3;
    int gr4 = lane >> 2, gc4 = lane & 3;
    int m0 = blockIdx.x * 128, n0 = blockIdx.y * 128;
    int z = p * 3 + blockIdx.z;   // (phi, tap)

    const __half* BH = g_wtH + (size_t)z * (ND * ND);
    const __half* BL = g_wtL + (size_t)z * (ND * ND);

    int lrow = tid >> 1;
    size_t aoff = (size_t)(m0 + lrow) * ND;
    size_t boff = (size_t)(n0 + lrow) * ND;
    int cByte = (tid & 1) * 32;
    const char* gAh = (const char*)(g_embH + aoff) + cByte;
    const char* gAl = (const char*)(g_embL + aoff) + cByte;
    const char* gBh = (const char*)(BH     + boff) + cByte;
    const char* gBl = (const char*)(BL     + boff) + cByte;
    uint32_t sOff = sbase + lrow * PITCH_B + cByte;

    int lm = lane & 15, lk = lane >> 4;
    uint32_t aFrag = sbase + (wm * 64 + lm) * PITCH_B + lk * 16;
    uint32_t bFrag = sbase + 20480 + (wn * 32 + lm) * PITCH_B + lk * 16;

    float acc[4][4][4];
#pragma unroll
    for (int i = 0; i < 4; i++)
#pragma unroll
        for (int j = 0; j < 4; j++)
#pragma unroll
            for (int q = 0; q < 4; q++) acc[i][j][q] = 0.f;

#define ISSUE3(stg, kb) do { \
        uint32_t so = sOff + (stg) * STAGE3_B; \
        int gb = (kb) * 64; \
        cp16(so,              gAh + gb,      16); \
        cp16(so + 16,         gAh + gb + 16, 16); \
        cp16(so + 10240,      gAl + gb,      16); \
        cp16(so + 10240 + 16, gAl + gb + 16, 16); \
        cp16(so + 20480,      gBh + gb,      16); \
        cp16(so + 20480 + 16, gBh + gb + 16, 16); \
        cp16(so + 30720,      gBl + gb,      16); \
        cp16(so + 30720 + 16, gBl + gb + 16, 16); \
        CP_COMMIT(); \
    } while (0)

    ISSUE3(0, 0);
    for (int kb = 0; kb < 16; kb++) {
        int st = kb & 1;
        __syncthreads();
        if (kb + 1 < 16) { ISSUE3((kb + 1) & 1, kb + 1); CP_WAIT1(); }
        else             { CP_WAIT0(); }
        __syncthreads();
        uint32_t sa = (uint32_t)st * STAGE3_B;
#pragma unroll
        for (int kp = 0; kp < 2; kp++) {
            uint32_t ah[4][4], al[4][4];
#pragma unroll
            for (int mt = 0; mt < 4; mt++) {
                uint32_t adr = aFrag + sa + mt * (16 * PITCH_B) + kp * 32;
                ldsm4(ah[mt], adr);
                ldsm4(al[mt], adr + 10240);
            }
#pragma unroll
            for (int ntp = 0; ntp < 2; ntp++) {
                uint32_t bh[4], bl[4];
                uint32_t badr = bFrag + sa + ntp * (16 * PITCH_B) + kp * 32;
                ldsm4(bh, badr);
                ldsm4(bl, badr + 10240);
#pragma unroll
                for (int mt = 0; mt < 4; mt++) {
                    MMA16816(acc[mt][2 * ntp],     ah[mt], bh[0], bh[2]);
                    MMA16816(acc[mt][2 * ntp],     al[mt], bh[0], bh[2]);
                    MMA16816(acc[mt][2 * ntp],     ah[mt], bl[0], bl[2]);
                    MMA16816(acc[mt][2 * ntp + 1], ah[mt], bh[1], bh[3]);
                    MMA16816(acc[mt][2 * ntp + 1], al[mt], bh[1], bh[3]);
                    MMA16816(acc[mt][2 * ntp + 1], ah[mt], bl[1], bl[3]);
                }
            }
        }
    }
#undef ISSUE3

    float* outz = g_tapw + (size_t)z * (NCB * ND);
#pragma unroll
    for (int mt = 0; mt < 4; mt++) {
#pragma unroll
        for (int h = 0; h < 2; h++) {
            int m = m0 + wm * 64 + mt * 16 + gr4 + 8 * h;
            float* crow = outz + ((size_t)m << 9);
#pragma unroll
            for (int nt = 0; nt < 4; nt++) {
                int c = n0 + wn * 32 + nt * 8 + 2 * gc4;
                *(float2*)(crow + c) =
                    make_float2(acc[mt][nt][2 * h], acc[mt][nt][2 * h + 1]);
            }
        }
    }
}

// ---------------- quantize: 1-term hi*hi GEMM + per-block top-2 candidates ----
#define STAGE1_B 20480
__global__ __launch_bounds__(256, 2) void k_quant1(int nTok) {
    extern __shared__ __align__(16) char dsm[];
    __shared__ unsigned long long smerge[128 * 8];
    uint32_t sbase = smem_u32(dsm);
    int tid = threadIdx.x;
    int lane = tid & 31, wid = tid >> 5;
    int wm = wid >> 2, wn = wid & 3;
    int gr4 = lane >> 2, gc4 = lane & 3;
    int m0 = blockIdx.x * 128, n0 = blockIdx.y * 128;

    int lrow = tid >> 1;
    int gm = m0 + lrow;
    int asz = (gm < nTok) ? 16 : 0;
    size_t aoff = (size_t)(gm < nTok ? gm : 0) * ND;
    size_t boff = (size_t)(n0 + lrow) * ND;
    int cByte = (tid & 1) * 32;
    const char* gAh = (const char*)(g_zH   + aoff) + cByte;
    const char* gBh = (const char*)(g_embH + boff) + cByte;
    uint32_t sOff = sbase + lrow * PITCH_B + cByte;

    int lm = lane & 15, lk = lane >> 4;
    uint32_t aFrag = sbase + (wm * 64 + lm) * PITCH_B + lk * 16;
    uint32_t bFrag = sbase + 10240 + (wn * 32 + lm) * PITCH_B + lk * 16;

    float acc[4][4][4];
#pragma unroll
    for (int i = 0; i < 4; i++)
#pragma unroll
        for (int j = 0; j < 4; j++)
#pragma unroll
            for (int q = 0; q < 4; q++) acc[i][j][q] = 0.f;

#define ISSUE1(stg, kb) do { \
        uint32_t so = sOff + (stg) * STAGE1_B; \
        int gb = (kb) * 64; \
        cp16(so,              gAh + gb,      asz); \
        cp16(so + 16,         gAh + gb + 16, asz); \
        cp16(so + 10240,      gBh + gb,      16); \
        cp16(so + 10240 + 16, gBh + gb + 16, 16); \
        CP_COMMIT(); \
    } while (0)

    ISSUE1(0, 0);
    for (int kb = 0; kb < 16; kb++) {
        int st = kb & 1;
        __syncthreads();
        if (kb + 1 < 16) { ISSUE1((kb + 1) & 1, kb + 1); CP_WAIT1(); }
        else             { CP_WAIT0(); }
        __syncthreads();
        uint32_t sa = (uint32_t)st * STAGE1_B;
#pragma unroll
        for (int kp = 0; kp < 2; kp++) {
            uint32_t ah[4][4];
#pragma unroll
            for (int mt = 0; mt < 4; mt++)
                ldsm4(ah[mt], aFrag + sa + mt * (16 * PITCH_B) + kp * 32);
#pragma unroll
            for (int ntp = 0; ntp < 2; ntp++) {
                uint32_t bh[4];
                ldsm4(bh, bFrag + sa + ntp * (16 * PITCH_B) + kp * 32);
#pragma unroll
                for (int mt = 0; mt < 4; mt++) {
                    MMA16816(acc[mt][2 * ntp],     ah[mt], bh[0], bh[2]);
                    MMA16816(acc[mt][2 * ntp + 1], ah[mt], bh[1], bh[3]);
                }
            }
        }
    }
#undef ISSUE1

#pragma unroll
    for (int mt = 0; mt < 4; mt++) {
#pragma unroll
        for (int h = 0; h < 2; h++) {
            int row = wm * 64 + mt * 16 + gr4 + 8 * h;
            unsigned long long k1 = 0xFFFFFFFFFFFFFFFFULL, k2 = k1;
#pragma unroll
            for (int nt = 0; nt < 4; nt++) {
#pragma unroll
                for (int e = 0; e < 2; e++) {
                    int c = n0 + wn * 32 + nt * 8 + 2 * gc4 + e;
                    float sc = fmaf(-2.f, acc[mt][nt][2 * h + e], __ldg(&g_esq[c]));
                    unsigned u = __float_as_uint(sc);
                    u = (u & 0x80000000u) ? ~u : (u | 0x80000000u);
                    unsigned long long key = ((unsigned long long)u << 32) | (unsigned)c;
                    if (key < k1) { k2 = k1; k1 = key; }
                    else if (key < k2) { k2 = key; }
                }
            }
#pragma unroll
            for (int o = 1; o <= 2; o <<= 1) {
                unsigned long long o1 = __shfl_xor_sync(0xffffffffu, k1, o);
                unsigned long long o2 = __shfl_xor_sync(0xffffffffu, k2, o);
                unsigned long long lo = (k1 < o1) ? k1 : o1;
                unsigned long long hi = (k1 < o1) ? o1 : k1;
                unsigned long long mn2 = (k2 < o2) ? k2 : o2;
                k1 = lo;
                k2 = (hi < mn2) ? hi : mn2;
            }
            if (gc4 == 0) {
                smerge[row * 8 + wn * 2]     = k1;
                smerge[row * 8 + wn * 2 + 1] = k2;
            }
        }
    }
    __syncthreads();
    if (tid < 128 && (m0 + tid) < nTok) {
        unsigned long long k1 = 0xFFFFFFFFFFFFFFFFULL, k2 = k1;
#pragma unroll
        for (int j = 0; j < 8; j++) {
            unsigned long long k = smerge[tid * 8 + j];
            if (k < k1) { k2 = k1; k1 = k; }
            else if (k < k2) { k2 = k; }
        }
        unsigned* dst = g_cand + (size_t)(m0 + tid) * 64 + blockIdx.y * 2;
        dst[0] = (unsigned)(k1 & 0xffffffffu);
        dst[1] = (unsigned)(k2 & 0xffffffffu);
    }
}

// ---------------- exact fp32 rescore of 64 candidates/token ----------------
__global__ void k_rescore(const float* __restrict__ embed, int nTok) {
    int tok = blockIdx.x * 8 + (threadIdx.x >> 5);
    int lane = threadIdx.x & 31;
    if (tok >= nTok) return;
    float z[16];
#pragma unroll
    for (int j = 0; j < 16; j++) {
        int a = tok * ND + lane + 32 * j;
        z[j] = __half2float(g_zH[a]) + __half2float(g_zL[a]);
    }
    float best = 3.4e38f; int bidx = 0x7fffffff;
    const unsigned* cand = g_cand + (size_t)tok * 64;
    for (int c = 0; c < 64; c++) {
        int idx = (int)cand[c];
        const float* e = embed + (size_t)idx * ND;
        float dot = 0.f;
#pragma unroll
        for (int j = 0; j < 16; j++)
            dot = fmaf(z[j], __ldg(e + lane + 32 * j), dot);
#pragma unroll
        for (int o = 16; o > 0; o >>= 1)
            dot += __shfl_xor_sync(0xffffffffu, dot, o);
        float sc = fmaf(-2.f, dot, g_esq[idx]);
        if (sc < best || (sc == best && idx < bidx)) { best = sc; bidx = idx; }
    }
    if (lane == 0) g_keys[tok] = (unsigned long long)(unsigned)bidx;
}

// ---------------- fused epilogue: gather tapw + interp + Phi mix + resid ------
// When outp != null also emits out = x - new_resid (fused final, si==9).
__global__ void k_phi_ep(const float* __restrict__ embed,
                         const float* __restrict__ bias,
                         int s, int p, const float* __restrict__ rsrc,
                         const float* __restrict__ xp, float* __restrict__ outp) {
    int total = NB * NL * 128;
    float ratio = (float)s * (1.0f / 512.0f);
    for (int t = blockIdx.x * blockDim.x + threadIdx.x; t < total;
         t += gridDim.x * blockDim.x) {
        int d4 = t & 127;
        int bl = t >> 7;
        int b = bl >> 9, l = bl & 511;
        const unsigned long long* kb = g_keys + b * s;
        float4 sum = *(const float4*)(bias + (d4 << 2));
        float4 qup = make_float4(0.f, 0.f, 0.f, 0.f);
#pragma unroll
        for (int k = 0; k < 3; k++) {
            int lp = l + k - 1;
            if ((unsigned)lp < 512u) {
                float pos = ((float)lp + 0.5f) * ratio - 0.5f;
                float fl = floorf(pos);
                int i0 = (int)fl;
                float f = pos - fl;
                int ia, ib;
                if (i0 < 0)          { ia = 0;     ib = 0;     f = 0.f; }
                else if (i0 >= s - 1){ ia = s - 1; ib = s - 1; f = 0.f; }
                else                 { ia = i0;    ib = i0 + 1; }
                float w1 = 1.0f - f, w2 = f;
                int ca = (int)(unsigned)(kb[ia] & 0xffffffffULL);
                const float* base = g_tapw + (size_t)(p * 3 + k) * (NCB * ND);
                float4 va = *((const float4*)(base + ((size_t)ca << 9)) + d4);
                sum.x += w1 * va.x; sum.y += w1 * va.y;
                sum.z += w1 * va.z; sum.w += w1 * va.w;
                if (k == 1) {
                    float4 ea = *((const float4*)(embed + ((size_t)ca << 9)) + d4);
                    qup.x = w1 * ea.x; qup.y = w1 * ea.y;
                    qup.z = w1 * ea.z; qup.w = w1 * ea.w;
                }
                if (w2 > 0.f) {
                    int cb = (int)(unsigned)(kb[ib] & 0xffffffffULL);
                    float4 vb = *((const float4*)(base + ((size_t)cb << 9)) + d4);
                    sum.x += w2 * vb.x; sum.y += w2 * vb.y;
                    sum.z += w2 * vb.z; sum.w += w2 * vb.w;
                    if (k == 1) {
                        float4 eb = *((const float4*)(embed + ((size_t)cb << 9)) + d4);
                        qup.x += w2 * eb.x; qup.y += w2 * eb.y;
                        qup.z += w2 * eb.z; qup.w += w2 * eb.w;
                    }
                }
            }
        }
        int adr = (bl << 9) + (d4 << 2);
        float4 rs = *(const float4*)(rsrc + adr);
        rs.x -= 0.5f * qup.x + 0.5f * sum.x;
        rs.y -= 0.5f * qup.y + 0.5f * sum.y;
        rs.z -= 0.5f * qup.z + 0.5f * sum.z;
        rs.w -= 0.5f * qup.w + 0.5f * sum.w;
        *(float4*)(g_resid + adr) = rs;
        if (outp) {
            float4 xv = *(const float4*)(xp + adr);
            *(float4*)(outp + adr) =
                make_float4(xv.x - rs.x, xv.y - rs.y, xv.z - rs.z, xv.w - rs.w);
        }
    }
}

// ---------------- host ----------------
extern "C" void kernel_launch(void* const* d_in, const int* in_sizes, int n_in,
                              void* d_out, int out_size) {
    const float* x     = (const float*)d_in[0];
    const float* embed = (const float*)d_in[1];
    const float* phi_w = (const float*)d_in[2];
    const float* phi_b = (const float*)d_in[3];
    float* out = (float*)d_out;

    float* residPtr = nullptr;
    cudaGetSymbolAddress((void**)&residPtr, g_resid);

    // Side stream + events for overlapping the tapw precompute with early scales.
    // Created once on the first (non-captured, correctness) call; reused in capture.
    static cudaStream_t s2 = nullptr;
    static cudaEvent_t ev0 = nullptr, evP[4] = {nullptr, nullptr, nullptr, nullptr};
    if (!s2) {
        cudaStreamCreateWithFlags(&s2, cudaStreamNonBlocking);
        cudaEventCreateWithFlags(&ev0, cudaEventDisableTiming);
        for (int p = 0; p < 4; p++)
            cudaEventCreateWithFlags(&evP[p], cudaEventDisableTiming);
        cudaFuncSetAttribute(k_gemm_pre,
                             cudaFuncAttributeMaxDynamicSharedMemorySize, 2 * STAGE3_B);
        cudaFuncSetAttribute(k_quant1,
                             cudaFuncAttributeMaxDynamicSharedMemorySize, 2 * STAGE1_B);
    }

    // Replicate np.linspace(1/12, 11/12, 4) + first-min tie-break in double.
    double start = 1.0 / 3.0 / 4.0;
    double stop  = 1.0 - 1.0 / 3.0 / 4.0;
    double step  = (stop - start) / 3.0;
    double ticks[4] = { start, start + step, start + 2.0 * step, stop };
    int scales[10] = { 1, 2, 4, 8, 16, 32, 64, 128, 256, 512 };
    int phi_idx[10];
    for (int si = 0; si < 10; si++) {
        double v = (double)si / 9.0;
        int bk = 0; double bd = fabs(ticks[0] - v);
        for (int k = 1; k < 4; k++) {
            double dd = fabs(ticks[k] - v);
            if (dd < bd) { bd = dd; bk = k; }
        }
        phi_idx[si] = bk;
    }
    // first scale index that uses each phi p
    int first_use[4] = { -1, -1, -1, -1 };
    for (int si = 0; si < 10; si++)
        if (first_use[phi_idx[si]] < 0) first_use[phi_idx[si]] = si;

    // setup on main stream
    k_setup_esq<<<512, 256>>>(embed);
    k_split_emb<<<1024, 256>>>(embed);
    k_setup_wt<<<1024, 256>>>(phi_w);

    // fork: precompute tapw per-phi on side stream, overlapping early scales
    cudaEventRecord(ev0, 0);
    cudaStreamWaitEvent(s2, ev0, 0);
    for (int p = 0; p < 4; p++) {
        k_gemm_pre<<<dim3(32, 4, 3), 256, 2 * STAGE3_B, s2>>>(p);
        cudaEventRecord(evP[p], s2);
    }

    for (int si = 0; si < 10; si++) {
        int s = scales[si];
        int nTok = NB * s;
        const float* src = (si == 0) ? x : residPtr;
        int p = phi_idx[si];

        if (s <= 16) {
            int segs = (NL / s) / 16;
            int t1 = NB * s * segs * 128;
            int b1 = (t1 + 255) / 256; if (b1 > 2048) b1 = 2048;
            k_down1<<<b1, 256>>>(s, segs, src);
            int t2 = NB * s * 128;
            int b2 = (t2 + 255) / 256;
            k_down2<<<b2, 256>>>(s, segs);
        } else {
            int total = NB * s * ND;
            int blk = (total + 255) / 256; if (blk > 8192) blk = 8192;
            k_down<<<blk, 256>>>(s, src);
        }

        int mTiles = (nTok + 127) / 128;
        k_quant1<<<dim3(mTiles, NCB / 128), 256, 2 * STAGE1_B>>>(nTok);
        k_rescore<<<(nTok + 7) / 8, 256>>>(embed, nTok);

        if (si == first_use[p])
            cudaStreamWaitEvent(0, evP[p], 0);   // join: tapw[p] ready

        bool last = (si == 9);
        k_phi_ep<<<4096, 256>>>(embed, phi_b + p * ND, s, p, src,
                                last ? x : (const float*)nullptr,
                                last ? out : (float*)nullptr);
    }
}